// round 13
// baseline (speedup 1.0000x reference)
#include <cuda_runtime.h>
#include <cuda_bf16.h>

// Problem constants (fixed shapes per reference):
//   z: [32,256,64,64] f32 -> flat [131072, 256]
//   codebook: [512, 256], n_i: [512], e_i: [512,256]
#define NR 131072
#define DD 256
#define KK 512
#define NV4 (NR * DD / 4)

// Output layout (concatenated reference tuple, all float32):
#define OFF_LOSS 33554432
#define OFF_ENC  33554433
#define OFF_CB   33685505
#define OFF_N    33816577
#define OFF_E    33817089

#define NSEG 8
#define PITCH_B 80              // 32 bf16 (64B) + 16B pad: ldmatrix conflict-free
#define SM_STAGE 10240          // 128 * 80 bytes, one matrix-split tile
#define SMO_Q(q)  ((unsigned)(q) * 4u * SM_STAGE)
#define SMO_AHI   0
#define SMO_ALO   SM_STAGE
#define SMO_BHI   (2 * SM_STAGE)
#define SMO_BLO   (3 * SM_STAGE)
#define SMO_HN    (8 * SM_STAGE)          // 81920
#define SM_TOTAL  (SMO_HN + KK * 4)       // 83968 B -> 2 CTAs/SM in 228KB

#define T1_ROWS 8               // tier-1 fixup: rows per block

// -------- device scratch (no allocations allowed) --------
static __device__ int    g_enc[NR];
static __device__ int    g_rowlist[NR];
static __device__ int    g_counts[KK];
static __device__ int    g_offsets[KK];
static __device__ int    g_cursor[KK];
static __device__ float  g_halfnorm[KK];
static __device__ double g_hnd[KK];
static __device__ int    g_fixn;
static __device__ int    g_fixrows[8192];
static __device__ int    g_fixn2;
static __device__ int    g_fixrows2[8192];
static __device__ float  g_epart[KK * NSEG * DD];
static __device__ double g_losspart[8192];
static __device__ __nv_bfloat16 g_cbhi[KK * DD];
static __device__ __nv_bfloat16 g_cblo[KK * DD];
static __device__ float  g_cbT[DD * KK];   // transposed codebook [d][k], fp32

// -------- PTX helpers --------
__device__ __forceinline__ unsigned smem_u32(const void* p) {
    unsigned a;
    asm("{ .reg .u64 t; cvta.to.shared.u64 t, %1; cvt.u32.u64 %0, t; }"
        : "=r"(a) : "l"(p));
    return a;
}
__device__ __forceinline__ void cp16(unsigned dst, const void* src) {
    asm volatile("cp.async.cg.shared.global [%0], [%1], 16;"
                 :: "r"(dst), "l"(__cvta_generic_to_global(src)));
}
__device__ __forceinline__ void cp_commit() { asm volatile("cp.async.commit_group;"); }
__device__ __forceinline__ void cp_wait_all() { asm volatile("cp.async.wait_group 0;"); }

__device__ __forceinline__ void ldm_x4(unsigned* r, unsigned addr) {
    asm volatile("ldmatrix.sync.aligned.m8n8.x4.shared.b16 {%0,%1,%2,%3}, [%4];"
                 : "=r"(r[0]), "=r"(r[1]), "=r"(r[2]), "=r"(r[3]) : "r"(addr));
}
__device__ __forceinline__ void mma16816(float* c, const unsigned* a,
                                         unsigned b0, unsigned b1) {
    asm volatile(
        "mma.sync.aligned.m16n8k16.row.col.f32.bf16.bf16.f32 "
        "{%0,%1,%2,%3}, {%4,%5,%6,%7}, {%8,%9}, {%0,%1,%2,%3};"
        : "+f"(c[0]), "+f"(c[1]), "+f"(c[2]), "+f"(c[3])
        : "r"(a[0]), "r"(a[1]), "r"(a[2]), "r"(a[3]), "r"(b0), "r"(b1));
}
__device__ __forceinline__ uint2 bf16x4_hi(float4 v, uint2& lo) {
    __nv_bfloat16 hx = __float2bfloat16(v.x), hy = __float2bfloat16(v.y);
    __nv_bfloat16 hz = __float2bfloat16(v.z), hw = __float2bfloat16(v.w);
    __nv_bfloat16 lx = __float2bfloat16(v.x - __bfloat162float(hx));
    __nv_bfloat16 ly = __float2bfloat16(v.y - __bfloat162float(hy));
    __nv_bfloat16 lz = __float2bfloat16(v.z - __bfloat162float(hz));
    __nv_bfloat16 lw = __float2bfloat16(v.w - __bfloat162float(hw));
    uint2 hi;
    hi.x = ((unsigned)__bfloat16_as_ushort(hy) << 16) | __bfloat16_as_ushort(hx);
    hi.y = ((unsigned)__bfloat16_as_ushort(hw) << 16) | __bfloat16_as_ushort(hz);
    lo.x = ((unsigned)__bfloat16_as_ushort(ly) << 16) | __bfloat16_as_ushort(lx);
    lo.y = ((unsigned)__bfloat16_as_ushort(lw) << 16) | __bfloat16_as_ushort(lz);
    return hi;
}
__device__ __forceinline__ unsigned long long pack2_dup(float x) {
    unsigned long long r;
    asm("mov.b64 %0, {%1, %1};" : "=l"(r) : "f"(x));
    return r;
}
__device__ __forceinline__ void ffma2(unsigned long long& d, unsigned long long a,
                                      unsigned long long b) {
    asm("fma.rn.f32x2 %0, %1, %2, %0;" : "+l"(d) : "l"(a), "l"(b));
}
__device__ __forceinline__ float2 unpack2(unsigned long long v) {
    float2 p;
    asm("mov.b64 {%0, %1}, %2;" : "=f"(p.x), "=f"(p.y) : "l"(v));
    return p;
}

// -------- prep: halfnorm + bf16 splits + transposed cb + per-replay init ------
__global__ void prep_kernel(const float* __restrict__ cb) {
    int k = blockIdx.x, t = threadIdx.x;
    float v = cb[k * DD + t];
    __nv_bfloat16 h = __float2bfloat16(v);
    g_cbhi[k * DD + t] = h;
    g_cblo[k * DD + t] = __float2bfloat16(v - __bfloat162float(h));
    g_cbT[t * KK + k] = v;
    double s = (double)v * (double)v;
    #pragma unroll
    for (int o = 16; o > 0; o >>= 1) s += __shfl_xor_sync(0xffffffffu, s, o);
    __shared__ double sm[8];
    if ((t & 31) == 0) sm[t >> 5] = s;
    __syncthreads();
    if (t == 0) {
        double tot = 0.0;
        #pragma unroll
        for (int i = 0; i < 8; i++) tot += sm[i];
        g_hnd[k] = 0.5 * tot;
        g_halfnorm[k] = (float)(0.5 * tot);
        g_counts[k] = 0;
        if (k == 0) { g_fixn = 0; g_fixn2 = 0; }
    }
}

__global__ void pad_kernel() {}

// -------- helpers for the pipelined argmin --------
__device__ __forceinline__ void stage_B(unsigned sb, int s, int tid) {
    int chunk = s >> 3, kt = s & 7;
    unsigned base = sb + SMO_Q(s & 1);
    #pragma unroll
    for (int i = 0; i < 4; i++) {
        int u = tid + i * 256;
        int split = u >> 9, uu = u & 511;
        int code = uu >> 2, c = uu & 3;
        const __nv_bfloat16* src = (split ? g_cblo : g_cbhi)
            + (chunk * 128 + code) * DD + kt * 32 + c * 8;
        cp16(base + (unsigned)((split ? SMO_BLO : SMO_BHI) + code * PITCH_B + c * 16), src);
    }
    cp_commit();
}
__device__ __forceinline__ void stage_A(unsigned char* smem, const float* z,
                                        int row0, int s, int tid) {
    int kt = s & 7;
    unsigned base = SMO_Q(s & 1);
    #pragma unroll 2
    for (int i = 0; i < 4; i++) {
        int u = tid + i * 256;
        int row = u >> 3, c = u & 7;
        float4 v = *(const float4*)(z + (long)(row0 + row) * DD + kt * 32 + c * 4);
        uint2 lo, hi = bf16x4_hi(v, lo);
        unsigned off = base + (unsigned)(row * PITCH_B + c * 8);
        *(uint2*)(smem + SMO_AHI + off) = hi;
        *(uint2*)(smem + SMO_ALO + off) = lo;
    }
}

// -------- HMMA bf16-split scoring + per-row argmax(top-2), pipelined --------
__global__ __launch_bounds__(256, 2) void argmin_tc_kernel(
        const float* __restrict__ z, float* __restrict__ enc_f) {
    extern __shared__ __align__(16) unsigned char smem[];
    const unsigned sb = smem_u32(smem);
    float* shn = (float*)(smem + SMO_HN);

    int tid = threadIdx.x, wid = tid >> 5, l = tid & 31;
    int row0 = blockIdx.x * 128;

    shn[tid] = g_halfnorm[tid];
    shn[tid + 256] = g_halfnorm[tid + 256];

    stage_B(sb, 0, tid);
    stage_A(smem, z, row0, 0, tid);

    unsigned aoff = (unsigned)(((wid << 4) + (l & 15)) * PITCH_B + ((l >> 4) << 4));
    unsigned boff = (unsigned)((((l & 7) + ((l >> 4) << 3)) * PITCH_B) + (((l >> 3) & 1) << 4));

    float bv[2], sv[2]; int bi[2];
    bv[0] = bv[1] = -3.4e38f; sv[0] = sv[1] = -3.4e38f; bi[0] = bi[1] = 0;

    float acc[16][4];
    #pragma unroll
    for (int n = 0; n < 16; n++)
        #pragma unroll
        for (int q = 0; q < 4; q++) acc[n][q] = 0.f;

    for (int s = 0; s < 32; s++) {
        cp_wait_all();
        __syncthreads();
        if (s + 1 < 32) {
            stage_B(sb, s + 1, tid);
            stage_A(smem, z, row0, s + 1, tid);
        }
        unsigned qb = SMO_Q(s & 1);
        unsigned ahi = sb + qb + SMO_AHI, alo = sb + qb + SMO_ALO;
        unsigned bhi = sb + qb + SMO_BHI, blo = sb + qb + SMO_BLO;

        #pragma unroll
        for (int ks = 0; ks < 2; ks++) {
            unsigned kb = (unsigned)(ks << 5);
            unsigned ah[4], al[4];
            ldm_x4(ah, ahi + aoff + kb);
            ldm_x4(al, alo + aoff + kb);
            #pragma unroll
            for (int pp = 0; pp < 4; pp++) {
                unsigned bha[4], bla[4], bhb[4], blb[4];
                unsigned boa = boff + (unsigned)((2 * pp) * 16 * PITCH_B) + kb;
                unsigned bob = boa + (unsigned)(16 * PITCH_B);
                ldm_x4(bha, bhi + boa);
                ldm_x4(bla, blo + boa);
                ldm_x4(bhb, bhi + bob);
                ldm_x4(blb, blo + bob);
                float* A0 = acc[4 * pp];     float* A1 = acc[4 * pp + 1];
                float* A2 = acc[4 * pp + 2]; float* A3 = acc[4 * pp + 3];
                mma16816(A0, ah, bha[0], bha[1]);
                mma16816(A1, ah, bha[2], bha[3]);
                mma16816(A2, ah, bhb[0], bhb[1]);
                mma16816(A3, ah, bhb[2], bhb[3]);
                mma16816(A0, ah, bla[0], bla[1]);
                mma16816(A1, ah, bla[2], bla[3]);
                mma16816(A2, ah, blb[0], blb[1]);
                mma16816(A3, ah, blb[2], blb[3]);
                mma16816(A0, al, bha[0], bha[1]);
                mma16816(A1, al, bha[2], bha[3]);
                mma16816(A2, al, bhb[0], bhb[1]);
                mma16816(A3, al, bhb[2], bhb[3]);
            }
        }

        if ((s & 7) == 7) {
            int col0 = (s >> 3) * 128;
            #pragma unroll
            for (int nt = 0; nt < 16; nt++) {
                int c0 = col0 + nt * 8 + ((l & 3) << 1);
                float2 hn2 = *(const float2*)&shn[c0];
                float s00 = acc[nt][0] - hn2.x, s01 = acc[nt][1] - hn2.y;
                float s10 = acc[nt][2] - hn2.x, s11 = acc[nt][3] - hn2.y;
                if (s00 > bv[0]) { sv[0] = bv[0]; bv[0] = s00; bi[0] = c0; }
                else if (s00 > sv[0]) sv[0] = s00;
                if (s01 > bv[0]) { sv[0] = bv[0]; bv[0] = s01; bi[0] = c0 + 1; }
                else if (s01 > sv[0]) sv[0] = s01;
                if (s10 > bv[1]) { sv[1] = bv[1]; bv[1] = s10; bi[1] = c0; }
                else if (s10 > sv[1]) sv[1] = s10;
                if (s11 > bv[1]) { sv[1] = bv[1]; bv[1] = s11; bi[1] = c0 + 1; }
                else if (s11 > sv[1]) sv[1] = s11;
            }
            #pragma unroll
            for (int nt = 0; nt < 16; nt++)
                #pragma unroll
                for (int q = 0; q < 4; q++) acc[nt][q] = 0.f;
        }
    }

    #pragma unroll
    for (int r = 0; r < 2; r++) {
        float v = bv[r], s2 = sv[r]; int idx = bi[r];
        #pragma unroll
        for (int off = 1; off <= 2; off <<= 1) {
            float v2  = __shfl_xor_sync(0xffffffffu, v, off);
            float s22 = __shfl_xor_sync(0xffffffffu, s2, off);
            int   i2  = __shfl_xor_sync(0xffffffffu, idx, off);
            if (v2 > v || (v2 == v && i2 < idx)) { s2 = fmaxf(v, s22); v = v2; idx = i2; }
            else { s2 = fmaxf(s2, v2); }
        }
        if ((l & 3) == 0) {
            int row = row0 + (wid << 4) + (l >> 2) + r * 8;
            g_enc[row] = idx;
            enc_f[row] = (float)idx;
            atomicAdd(&g_counts[idx], 1);
            if (v - s2 < 5e-4f) {
                int p = atomicAdd(&g_fixn, 1);
                if (p < 8192) g_fixrows[p] = row;
            }
        }
    }
}

// -------- tier-1 fixup: fp32 (FFMA2) full rescore, 8 rows per block --------
// Decides rows with fp32 gap >= 1.2e-4 (7+ sigma of fp32 dot error); the rest
// go to the fp64 tier-2 list. Codebook read via transposed cbT (coalesced).
__global__ __launch_bounds__(256) void fixup32_kernel(
        const float* __restrict__ z, float* __restrict__ enc_f) {
    __shared__ unsigned long long zsh2[T1_ROWS][DD];   // z duplicated as f32x2
    __shared__ float shn[KK];
    __shared__ float red_v[8][T1_ROWS];
    __shared__ float red_s[8][T1_ROWS];
    __shared__ int   red_i[8][T1_ROWS];

    int t = threadIdx.x, wid = t >> 5, l = t & 31;
    int nfix = min(g_fixn, 8192);

    shn[t] = g_halfnorm[t];
    shn[t + 256] = g_halfnorm[t + 256];

    for (int g0 = blockIdx.x * T1_ROWS; g0 < nfix; g0 += gridDim.x * T1_ROWS) {
        int nr = min(T1_ROWS, nfix - g0);
        __syncthreads();                      // prev iteration readers done
        for (int i = t; i < nr * DD; i += 256) {
            int r = i >> 8, d = i & 255;
            zsh2[r][d] = pack2_dup(z[(long)g_fixrows[g0 + r] * DD + d]);
        }
        __syncthreads();

        // codes 2t, 2t+1 for this thread
        unsigned long long dot2[T1_ROWS];
        #pragma unroll
        for (int r = 0; r < T1_ROWS; r++) dot2[r] = 0ull;
        for (int d = 0; d < DD; d++) {
            unsigned long long cv = *(const unsigned long long*)&g_cbT[d * KK + 2 * t];
            #pragma unroll
            for (int r = 0; r < T1_ROWS; r++) ffma2(dot2[r], zsh2[r][d], cv);
        }
        float hn0 = shn[2 * t], hn1 = shn[2 * t + 1];

        #pragma unroll
        for (int r = 0; r < T1_ROWS; r++) {
            float2 p = unpack2(dot2[r]);
            float s0 = p.x - hn0, s1 = p.y - hn1;
            float v = s0, s2 = -3.4e38f; int idx = 2 * t;
            if (s1 > v) { s2 = v; v = s1; idx = 2 * t + 1; }
            else s2 = s1;
            // warp reduce
            #pragma unroll
            for (int off = 16; off > 0; off >>= 1) {
                float v2  = __shfl_xor_sync(0xffffffffu, v, off);
                float s22 = __shfl_xor_sync(0xffffffffu, s2, off);
                int   i2  = __shfl_xor_sync(0xffffffffu, idx, off);
                if (v2 > v || (v2 == v && i2 < idx)) { s2 = fmaxf(v, s22); v = v2; idx = i2; }
                else { s2 = fmaxf(s2, v2); }
            }
            if (l == 0) { red_v[wid][r] = v; red_s[wid][r] = s2; red_i[wid][r] = idx; }
        }
        __syncthreads();

        if (t < nr) {
            int r = t;
            float v = -3.4e38f, s2 = -3.4e38f; int idx = 0;
            #pragma unroll
            for (int w = 0; w < 8; w++) {
                float v2 = red_v[w][r], s22 = red_s[w][r];
                int i2 = red_i[w][r];
                if (v2 > v || (v2 == v && i2 < idx)) { s2 = fmaxf(v, s22); v = v2; idx = i2; }
                else { s2 = fmaxf(s2, v2); }
            }
            int row = g_fixrows[g0 + r];
            if (v - s2 < 1.2e-4f) {           // still ambiguous: fp64 tier
                int p = atomicAdd(&g_fixn2, 1);
                if (p < 8192) g_fixrows2[p] = row;
            } else {
                int old = g_enc[row];
                if (idx != old) {
                    atomicSub(&g_counts[old], 1);
                    atomicAdd(&g_counts[idx], 1);
                    g_enc[row] = idx;
                    enc_f[row] = (float)idx;
                }
            }
        }
    }
}

// -------- tier-2: exact fp64 re-argmax (dot form) for residual rows --------
__global__ void fixup_kernel(const float* __restrict__ z, const float* __restrict__ cb,
                             float* __restrict__ enc_f) {
    __shared__ double sval[256];
    __shared__ int    sidx[256];
    __shared__ float  zsh[DD];
    int nfix = min(g_fixn2, 8192);
    int t = threadIdx.x;
    for (int e = blockIdx.x; e < nfix; e += gridDim.x) {
        int row = g_fixrows2[e];
        zsh[t] = z[row * DD + t];
        __syncthreads();
        double bestv = -1e300; int besti = 0;
        #pragma unroll
        for (int kb = 0; kb < 2; kb++) {
            int k = t + kb * 256;
            const float* cr = cb + k * DD;
            double a0 = 0.0, a1 = 0.0, a2 = 0.0, a3 = 0.0;
            #pragma unroll 4
            for (int dd = 0; dd < DD; dd += 4) {
                a0 += (double)zsh[dd]     * (double)cr[dd];
                a1 += (double)zsh[dd + 1] * (double)cr[dd + 1];
                a2 += (double)zsh[dd + 2] * (double)cr[dd + 2];
                a3 += (double)zsh[dd + 3] * (double)cr[dd + 3];
            }
            double s = ((a0 + a1) + (a2 + a3)) - g_hnd[k];
            if (s > bestv || (s == bestv && k < besti)) { bestv = s; besti = k; }
        }
        sval[t] = bestv; sidx[t] = besti;
        __syncthreads();
        for (int off = 128; off > 0; off >>= 1) {
            if (t < off) {
                if (sval[t + off] > sval[t] ||
                    (sval[t + off] == sval[t] && sidx[t + off] < sidx[t])) {
                    sval[t] = sval[t + off]; sidx[t] = sidx[t + off];
                }
            }
            __syncthreads();
        }
        if (t == 0) {
            int old = g_enc[row];
            if (sidx[0] != old) {
                atomicSub(&g_counts[old], 1);
                atomicAdd(&g_counts[sidx[0]], 1);
                g_enc[row] = sidx[0];
                enc_f[row] = (float)sidx[0];
            }
        }
        __syncthreads();
    }
}

// -------- exclusive scan over 512 bins --------
__global__ void prefix_kernel() {
    __shared__ int a[KK];
    int t = threadIdx.x;
    int c = g_counts[t];
    a[t] = c;
    __syncthreads();
    for (int off = 1; off < KK; off <<= 1) {
        int v = (t >= off) ? a[t - off] : 0;
        __syncthreads();
        a[t] += v;
        __syncthreads();
    }
    int ex = a[t] - c;
    g_offsets[t] = ex;
    g_cursor[t] = ex;
}

// -------- scatter rows into per-code buckets --------
__global__ void scatter_kernel() {
    int stride = gridDim.x * blockDim.x;
    for (int i = blockIdx.x * blockDim.x + threadIdx.x; i < NR; i += stride) {
        int k = g_enc[i];
        int pos = atomicAdd(&g_cursor[k], 1);
        g_rowlist[pos] = i;
    }
}

// -------- per-code EMA: balanced partial sums --------
__global__ void update_partial_kernel(const float* __restrict__ z) {
    int k = blockIdx.x / NSEG, s = blockIdx.x % NSEG, t = threadIdx.x;
    int base = g_offsets[k];
    int cnt = g_counts[k];
    int lo = base + (int)((long long)cnt * s / NSEG);
    int hi = base + (int)((long long)cnt * (s + 1) / NSEG);
    float acc = 0.f;
    int i = lo;
    for (; i + 4 <= hi; i += 4) {
        int r0 = g_rowlist[i],     r1 = g_rowlist[i + 1];
        int r2 = g_rowlist[i + 2], r3 = g_rowlist[i + 3];
        float v0 = z[r0 * DD + t], v1 = z[r1 * DD + t];
        float v2 = z[r2 * DD + t], v3 = z[r3 * DD + t];
        acc += v0; acc += v1; acc += v2; acc += v3;
    }
    for (; i < hi; i++) acc += z[g_rowlist[i] * DD + t];
    g_epart[blockIdx.x * DD + t] = acc;
}

// -------- combine partials, write e_new / cb_new / n_new --------
__global__ void update_reduce_kernel(const float* __restrict__ n_i,
                                     const float* __restrict__ e_i,
                                     float* __restrict__ out_e, float* __restrict__ out_cb,
                                     float* __restrict__ out_n) {
    int k = blockIdx.x, t = threadIdx.x;
    const float* pp = g_epart + (k * NSEG) * DD + t;
    float acc = 0.f;
    #pragma unroll
    for (int i = 0; i < NSEG; i += 4) {
        float s01 = pp[i * DD] + pp[(i + 1) * DD];
        float s23 = pp[(i + 2) * DD] + pp[(i + 3) * DD];
        acc += s01 + s23;
    }
    const float C1 = (float)(1.0 - 0.99);
    const float NS = (float)(32.0 / (32.0 + 512.0 * 1e-5));
    float nnew = (0.99f * n_i[k] + C1 * (float)g_counts[k] + 1e-5f) * NS;
    float enew = 0.99f * e_i[k * DD + t] + C1 * acc;
    out_e[k * DD + t]  = enew;
    out_cb[k * DD + t] = enew / nnew;
    if (t == 0) out_n[k] = nnew;
}

// -------- gather codes, STE output, commitment-loss partials (linear z) -------
__global__ void gather_kernel(const float* __restrict__ z, const float* __restrict__ cb,
                              float* __restrict__ out_code) {
    float part = 0.f;
    int stride = gridDim.x * blockDim.x;
    for (int idx = blockIdx.x * blockDim.x + threadIdx.x; idx < NV4; idx += stride) {
        float4 zv = ((const float4*)z)[idx];
        int row = idx >> 6;
        int d = (idx & 63) << 2;
        int k = g_enc[row];
        float4 cv = *(const float4*)(cb + k * DD + d);
        float4 o;
        o.x = zv.x + (cv.x - zv.x);
        o.y = zv.y + (cv.y - zv.y);
        o.z = zv.z + (cv.z - zv.z);
        o.w = zv.w + (cv.w - zv.w);
        ((float4*)out_code)[idx] = o;
        float dx = zv.x - cv.x, dy = zv.y - cv.y;
        float dz = zv.z - cv.z, dw = zv.w - cv.w;
        part += dx * dx + dy * dy + dz * dz + dw * dw;
    }
    #pragma unroll
    for (int o = 16; o > 0; o >>= 1) part += __shfl_xor_sync(0xffffffffu, part, o);
    __shared__ float sm[8];
    if ((threadIdx.x & 31) == 0) sm[threadIdx.x >> 5] = part;
    __syncthreads();
    if (threadIdx.x == 0) {
        float tot = 0.f;
        #pragma unroll
        for (int i = 0; i < 8; i++) tot += sm[i];
        g_losspart[blockIdx.x] = (double)tot;
    }
}

__global__ void finalize_kernel(float* __restrict__ out_loss) {
    __shared__ double sm[256];
    double s = 0.0;
    for (int i = threadIdx.x; i < 8192; i += 256) s += g_losspart[i];
    sm[threadIdx.x] = s;
    __syncthreads();
    for (int off = 128; off > 0; off >>= 1) {
        if (threadIdx.x < off) sm[threadIdx.x] += sm[threadIdx.x + off];
        __syncthreads();
    }
    if (threadIdx.x == 0) out_loss[0] = 0.25f * (float)(sm[0] / 33554432.0);
}

extern "C" void kernel_launch(void* const* d_in, const int* in_sizes, int n_in,
                              void* d_out, int out_size) {
    const float* z   = (const float*)d_in[0];
    const float* cb  = (const float*)d_in[1];
    const float* n_i = (const float*)d_in[2];
    const float* e_i = (const float*)d_in[3];
    float* out = (float*)d_out;

    cudaFuncSetAttribute(argmin_tc_kernel,
                         cudaFuncAttributeMaxDynamicSharedMemorySize, SM_TOTAL);

    prep_kernel<<<KK, 256>>>(cb);                                    // #1
    pad_kernel<<<1, 32>>>();                                         // #2
    pad_kernel<<<1, 32>>>();                                         // #3
    argmin_tc_kernel<<<NR / 128, 256, SM_TOTAL>>>(z, out + OFF_ENC); // #4 <- ncu
    fixup32_kernel<<<256, 256>>>(z, out + OFF_ENC);                  // #5
    fixup_kernel<<<128, 256>>>(z, cb, out + OFF_ENC);                // #6
    prefix_kernel<<<1, KK>>>();
    scatter_kernel<<<128, 256>>>();
    update_partial_kernel<<<KK * NSEG, 256>>>(z);
    update_reduce_kernel<<<KK, 256>>>(n_i, e_i, out + OFF_E, out + OFF_CB, out + OFF_N);
    gather_kernel<<<8192, 256>>>(z, cb, out);
    finalize_kernel<<<1, 256>>>(out + OFF_LOSS);
}

// round 14
// speedup vs baseline: 1.0018x; 1.0018x over previous
#include <cuda_runtime.h>
#include <cuda_bf16.h>

// Problem constants (fixed shapes per reference):
//   z: [32,256,64,64] f32 -> flat [131072, 256]
//   codebook: [512, 256], n_i: [512], e_i: [512,256]
#define NR 131072
#define DD 256
#define KK 512
#define NV4 (NR * DD / 4)

// Output layout (concatenated reference tuple, all float32):
#define OFF_LOSS 33554432
#define OFF_ENC  33554433
#define OFF_CB   33685505
#define OFF_N    33816577
#define OFF_E    33817089

#define NSEG 8
#define PITCH_B 80              // 32 bf16 (64B) + 16B pad: ldmatrix conflict-free
#define SM_STAGE 10240          // 128 * 80 bytes, one matrix-split tile
#define SMO_Q(q)  ((unsigned)(q) * 4u * SM_STAGE)
#define SMO_AHI   0
#define SMO_ALO   SM_STAGE
#define SMO_BHI   (2 * SM_STAGE)
#define SMO_BLO   (3 * SM_STAGE)
#define SMO_HN    (8 * SM_STAGE)          // 81920
#define SM_TOTAL  (SMO_HN + KK * 4)       // 83968 B -> 2 CTAs/SM in 228KB

#define T1_ROWS 8               // tier-1 fixup: rows per block

// -------- device scratch (no allocations allowed) --------
static __device__ int    g_enc[NR];
static __device__ int    g_rowlist[NR];
static __device__ int    g_counts[KK];
static __device__ int    g_offsets[KK];
static __device__ int    g_cursor[KK];
static __device__ float  g_halfnorm[KK];
static __device__ double g_hnd[KK];
static __device__ int    g_fixn;
static __device__ int    g_fixrows[8192];
static __device__ int    g_fixn2;
static __device__ int    g_fixrows2[8192];
static __device__ float  g_epart[KK * NSEG * DD];
static __device__ double g_losspart[8192];
static __device__ __nv_bfloat16 g_cbhi[KK * DD];
static __device__ __nv_bfloat16 g_cblo[KK * DD];
static __device__ float  g_cbT[DD * KK];   // transposed codebook [d][k], fp32

// -------- PTX helpers --------
__device__ __forceinline__ unsigned smem_u32(const void* p) {
    unsigned a;
    asm("{ .reg .u64 t; cvta.to.shared.u64 t, %1; cvt.u32.u64 %0, t; }"
        : "=r"(a) : "l"(p));
    return a;
}
__device__ __forceinline__ void cp16(unsigned dst, const void* src) {
    asm volatile("cp.async.cg.shared.global [%0], [%1], 16;"
                 :: "r"(dst), "l"(__cvta_generic_to_global(src)));
}
__device__ __forceinline__ void cp_commit() { asm volatile("cp.async.commit_group;"); }
__device__ __forceinline__ void cp_wait_all() { asm volatile("cp.async.wait_group 0;"); }

__device__ __forceinline__ void ldm_x4(unsigned* r, unsigned addr) {
    asm volatile("ldmatrix.sync.aligned.m8n8.x4.shared.b16 {%0,%1,%2,%3}, [%4];"
                 : "=r"(r[0]), "=r"(r[1]), "=r"(r[2]), "=r"(r[3]) : "r"(addr));
}
__device__ __forceinline__ void mma16816(float* c, const unsigned* a,
                                         unsigned b0, unsigned b1) {
    asm volatile(
        "mma.sync.aligned.m16n8k16.row.col.f32.bf16.bf16.f32 "
        "{%0,%1,%2,%3}, {%4,%5,%6,%7}, {%8,%9}, {%0,%1,%2,%3};"
        : "+f"(c[0]), "+f"(c[1]), "+f"(c[2]), "+f"(c[3])
        : "r"(a[0]), "r"(a[1]), "r"(a[2]), "r"(a[3]), "r"(b0), "r"(b1));
}
__device__ __forceinline__ uint2 bf16x4_hi(float4 v, uint2& lo) {
    __nv_bfloat16 hx = __float2bfloat16(v.x), hy = __float2bfloat16(v.y);
    __nv_bfloat16 hz = __float2bfloat16(v.z), hw = __float2bfloat16(v.w);
    __nv_bfloat16 lx = __float2bfloat16(v.x - __bfloat162float(hx));
    __nv_bfloat16 ly = __float2bfloat16(v.y - __bfloat162float(hy));
    __nv_bfloat16 lz = __float2bfloat16(v.z - __bfloat162float(hz));
    __nv_bfloat16 lw = __float2bfloat16(v.w - __bfloat162float(hw));
    uint2 hi;
    hi.x = ((unsigned)__bfloat16_as_ushort(hy) << 16) | __bfloat16_as_ushort(hx);
    hi.y = ((unsigned)__bfloat16_as_ushort(hw) << 16) | __bfloat16_as_ushort(hz);
    lo.x = ((unsigned)__bfloat16_as_ushort(ly) << 16) | __bfloat16_as_ushort(lx);
    lo.y = ((unsigned)__bfloat16_as_ushort(lw) << 16) | __bfloat16_as_ushort(lz);
    return hi;
}
__device__ __forceinline__ unsigned long long pack2_dup(float x) {
    unsigned long long r;
    asm("mov.b64 %0, {%1, %1};" : "=l"(r) : "f"(x));
    return r;
}
__device__ __forceinline__ void ffma2(unsigned long long& d, unsigned long long a,
                                      unsigned long long b) {
    asm("fma.rn.f32x2 %0, %1, %2, %0;" : "+l"(d) : "l"(a), "l"(b));
}
__device__ __forceinline__ float2 unpack2(unsigned long long v) {
    float2 p;
    asm("mov.b64 {%0, %1}, %2;" : "=f"(p.x), "=f"(p.y) : "l"(v));
    return p;
}

// -------- prep: halfnorm + bf16 splits + transposed cb + per-replay init ------
__global__ void prep_kernel(const float* __restrict__ cb) {
    int k = blockIdx.x, t = threadIdx.x;
    float v = cb[k * DD + t];
    __nv_bfloat16 h = __float2bfloat16(v);
    g_cbhi[k * DD + t] = h;
    g_cblo[k * DD + t] = __float2bfloat16(v - __bfloat162float(h));
    g_cbT[t * KK + k] = v;
    double s = (double)v * (double)v;
    #pragma unroll
    for (int o = 16; o > 0; o >>= 1) s += __shfl_xor_sync(0xffffffffu, s, o);
    __shared__ double sm[8];
    if ((t & 31) == 0) sm[t >> 5] = s;
    __syncthreads();
    if (t == 0) {
        double tot = 0.0;
        #pragma unroll
        for (int i = 0; i < 8; i++) tot += sm[i];
        g_hnd[k] = 0.5 * tot;
        g_halfnorm[k] = (float)(0.5 * tot);
        g_counts[k] = 0;
        if (k == 0) { g_fixn = 0; g_fixn2 = 0; }
    }
}

__global__ void pad_kernel() {}

// -------- helpers for the pipelined argmin --------
__device__ __forceinline__ void stage_B(unsigned sb, int s, int tid) {
    int chunk = s >> 3, kt = s & 7;
    unsigned base = sb + SMO_Q(s & 1);
    #pragma unroll
    for (int i = 0; i < 4; i++) {
        int u = tid + i * 256;
        int split = u >> 9, uu = u & 511;
        int code = uu >> 2, c = uu & 3;
        const __nv_bfloat16* src = (split ? g_cblo : g_cbhi)
            + (chunk * 128 + code) * DD + kt * 32 + c * 8;
        cp16(base + (unsigned)((split ? SMO_BLO : SMO_BHI) + code * PITCH_B + c * 16), src);
    }
    cp_commit();
}
__device__ __forceinline__ void stage_A(unsigned char* smem, const float* z,
                                        int row0, int s, int tid) {
    int kt = s & 7;
    unsigned base = SMO_Q(s & 1);
    #pragma unroll 2
    for (int i = 0; i < 4; i++) {
        int u = tid + i * 256;
        int row = u >> 3, c = u & 7;
        float4 v = *(const float4*)(z + (long)(row0 + row) * DD + kt * 32 + c * 4);
        uint2 lo, hi = bf16x4_hi(v, lo);
        unsigned off = base + (unsigned)(row * PITCH_B + c * 8);
        *(uint2*)(smem + SMO_AHI + off) = hi;
        *(uint2*)(smem + SMO_ALO + off) = lo;
    }
}

// -------- HMMA bf16-split scoring + per-row argmax(top-2), pipelined --------
__global__ __launch_bounds__(256, 2) void argmin_tc_kernel(
        const float* __restrict__ z, float* __restrict__ enc_f) {
    extern __shared__ __align__(16) unsigned char smem[];
    const unsigned sb = smem_u32(smem);
    float* shn = (float*)(smem + SMO_HN);

    int tid = threadIdx.x, wid = tid >> 5, l = tid & 31;
    int row0 = blockIdx.x * 128;

    shn[tid] = g_halfnorm[tid];
    shn[tid + 256] = g_halfnorm[tid + 256];

    stage_B(sb, 0, tid);
    stage_A(smem, z, row0, 0, tid);

    unsigned aoff = (unsigned)(((wid << 4) + (l & 15)) * PITCH_B + ((l >> 4) << 4));
    unsigned boff = (unsigned)((((l & 7) + ((l >> 4) << 3)) * PITCH_B) + (((l >> 3) & 1) << 4));

    float bv[2], sv[2]; int bi[2];
    bv[0] = bv[1] = -3.4e38f; sv[0] = sv[1] = -3.4e38f; bi[0] = bi[1] = 0;

    float acc[16][4];
    #pragma unroll
    for (int n = 0; n < 16; n++)
        #pragma unroll
        for (int q = 0; q < 4; q++) acc[n][q] = 0.f;

    for (int s = 0; s < 32; s++) {
        cp_wait_all();
        __syncthreads();
        if (s + 1 < 32) {
            stage_B(sb, s + 1, tid);
            stage_A(smem, z, row0, s + 1, tid);
        }
        unsigned qb = SMO_Q(s & 1);
        unsigned ahi = sb + qb + SMO_AHI, alo = sb + qb + SMO_ALO;
        unsigned bhi = sb + qb + SMO_BHI, blo = sb + qb + SMO_BLO;

        #pragma unroll
        for (int ks = 0; ks < 2; ks++) {
            unsigned kb = (unsigned)(ks << 5);
            unsigned ah[4], al[4];
            ldm_x4(ah, ahi + aoff + kb);
            ldm_x4(al, alo + aoff + kb);
            #pragma unroll
            for (int pp = 0; pp < 4; pp++) {
                unsigned bha[4], bla[4], bhb[4], blb[4];
                unsigned boa = boff + (unsigned)((2 * pp) * 16 * PITCH_B) + kb;
                unsigned bob = boa + (unsigned)(16 * PITCH_B);
                ldm_x4(bha, bhi + boa);
                ldm_x4(bla, blo + boa);
                ldm_x4(bhb, bhi + bob);
                ldm_x4(blb, blo + bob);
                float* A0 = acc[4 * pp];     float* A1 = acc[4 * pp + 1];
                float* A2 = acc[4 * pp + 2]; float* A3 = acc[4 * pp + 3];
                mma16816(A0, ah, bha[0], bha[1]);
                mma16816(A1, ah, bha[2], bha[3]);
                mma16816(A2, ah, bhb[0], bhb[1]);
                mma16816(A3, ah, bhb[2], bhb[3]);
                mma16816(A0, ah, bla[0], bla[1]);
                mma16816(A1, ah, bla[2], bla[3]);
                mma16816(A2, ah, blb[0], blb[1]);
                mma16816(A3, ah, blb[2], blb[3]);
                mma16816(A0, al, bha[0], bha[1]);
                mma16816(A1, al, bha[2], bha[3]);
                mma16816(A2, al, bhb[0], bhb[1]);
                mma16816(A3, al, bhb[2], bhb[3]);
            }
        }

        if ((s & 7) == 7) {
            int col0 = (s >> 3) * 128;
            #pragma unroll
            for (int nt = 0; nt < 16; nt++) {
                int c0 = col0 + nt * 8 + ((l & 3) << 1);
                float2 hn2 = *(const float2*)&shn[c0];
                float s00 = acc[nt][0] - hn2.x, s01 = acc[nt][1] - hn2.y;
                float s10 = acc[nt][2] - hn2.x, s11 = acc[nt][3] - hn2.y;
                if (s00 > bv[0]) { sv[0] = bv[0]; bv[0] = s00; bi[0] = c0; }
                else if (s00 > sv[0]) sv[0] = s00;
                if (s01 > bv[0]) { sv[0] = bv[0]; bv[0] = s01; bi[0] = c0 + 1; }
                else if (s01 > sv[0]) sv[0] = s01;
                if (s10 > bv[1]) { sv[1] = bv[1]; bv[1] = s10; bi[1] = c0; }
                else if (s10 > sv[1]) sv[1] = s10;
                if (s11 > bv[1]) { sv[1] = bv[1]; bv[1] = s11; bi[1] = c0 + 1; }
                else if (s11 > sv[1]) sv[1] = s11;
            }
            #pragma unroll
            for (int nt = 0; nt < 16; nt++)
                #pragma unroll
                for (int q = 0; q < 4; q++) acc[nt][q] = 0.f;
        }
    }

    #pragma unroll
    for (int r = 0; r < 2; r++) {
        float v = bv[r], s2 = sv[r]; int idx = bi[r];
        #pragma unroll
        for (int off = 1; off <= 2; off <<= 1) {
            float v2  = __shfl_xor_sync(0xffffffffu, v, off);
            float s22 = __shfl_xor_sync(0xffffffffu, s2, off);
            int   i2  = __shfl_xor_sync(0xffffffffu, idx, off);
            if (v2 > v || (v2 == v && i2 < idx)) { s2 = fmaxf(v, s22); v = v2; idx = i2; }
            else { s2 = fmaxf(s2, v2); }
        }
        if ((l & 3) == 0) {
            int row = row0 + (wid << 4) + (l >> 2) + r * 8;
            g_enc[row] = idx;
            enc_f[row] = (float)idx;
            atomicAdd(&g_counts[idx], 1);
            if (v - s2 < 5e-4f) {
                int p = atomicAdd(&g_fixn, 1);
                if (p < 8192) g_fixrows[p] = row;
            }
        }
    }
}

// -------- tier-1 fixup: fp32 (FFMA2) full rescore, 8 rows per block --------
// d-loop batched by 8: 8 independent codebook LDGs in flight (MLP=8) before
// the 64 dependent FFMA2s -- hides L2 latency (Round-13 version had MLP=1).
__global__ __launch_bounds__(256) void fixup32_kernel(
        const float* __restrict__ z, float* __restrict__ enc_f) {
    __shared__ unsigned long long zsh2[T1_ROWS][DD];   // z duplicated as f32x2
    __shared__ float shn[KK];
    __shared__ float red_v[8][T1_ROWS];
    __shared__ float red_s[8][T1_ROWS];
    __shared__ int   red_i[8][T1_ROWS];

    int t = threadIdx.x, wid = t >> 5, l = t & 31;
    int nfix = min(g_fixn, 8192);

    shn[t] = g_halfnorm[t];
    shn[t + 256] = g_halfnorm[t + 256];

    for (int g0 = blockIdx.x * T1_ROWS; g0 < nfix; g0 += gridDim.x * T1_ROWS) {
        int nr = min(T1_ROWS, nfix - g0);
        __syncthreads();                      // prev iteration readers done
        for (int i = t; i < nr * DD; i += 256) {
            int r = i >> 8, d = i & 255;
            zsh2[r][d] = pack2_dup(z[(long)g_fixrows[g0 + r] * DD + d]);
        }
        __syncthreads();

        // codes 2t, 2t+1 for this thread
        unsigned long long dot2[T1_ROWS];
        #pragma unroll
        for (int r = 0; r < T1_ROWS; r++) dot2[r] = 0ull;
        for (int d0 = 0; d0 < DD; d0 += 8) {
            unsigned long long cv[8];
            #pragma unroll
            for (int j = 0; j < 8; j++)
                cv[j] = *(const unsigned long long*)&g_cbT[(d0 + j) * KK + 2 * t];
            #pragma unroll
            for (int j = 0; j < 8; j++)
                #pragma unroll
                for (int r = 0; r < T1_ROWS; r++) ffma2(dot2[r], zsh2[r][d0 + j], cv[j]);
        }
        float hn0 = shn[2 * t], hn1 = shn[2 * t + 1];

        #pragma unroll
        for (int r = 0; r < T1_ROWS; r++) {
            float2 p = unpack2(dot2[r]);
            float s0 = p.x - hn0, s1 = p.y - hn1;
            float v = s0, s2 = -3.4e38f; int idx = 2 * t;
            if (s1 > v) { s2 = v; v = s1; idx = 2 * t + 1; }
            else s2 = s1;
            #pragma unroll
            for (int off = 16; off > 0; off >>= 1) {
                float v2  = __shfl_xor_sync(0xffffffffu, v, off);
                float s22 = __shfl_xor_sync(0xffffffffu, s2, off);
                int   i2  = __shfl_xor_sync(0xffffffffu, idx, off);
                if (v2 > v || (v2 == v && i2 < idx)) { s2 = fmaxf(v, s22); v = v2; idx = i2; }
                else { s2 = fmaxf(s2, v2); }
            }
            if (l == 0) { red_v[wid][r] = v; red_s[wid][r] = s2; red_i[wid][r] = idx; }
        }
        __syncthreads();

        if (t < nr) {
            int r = t;
            float v = -3.4e38f, s2 = -3.4e38f; int idx = 0;
            #pragma unroll
            for (int w = 0; w < 8; w++) {
                float v2 = red_v[w][r], s22 = red_s[w][r];
                int i2 = red_i[w][r];
                if (v2 > v || (v2 == v && i2 < idx)) { s2 = fmaxf(v, s22); v = v2; idx = i2; }
                else { s2 = fmaxf(s2, v2); }
            }
            int row = g_fixrows[g0 + r];
            if (v - s2 < 1.2e-4f) {           // still ambiguous: fp64 tier
                int p = atomicAdd(&g_fixn2, 1);
                if (p < 8192) g_fixrows2[p] = row;
            } else {
                int old = g_enc[row];
                if (idx != old) {
                    atomicSub(&g_counts[old], 1);
                    atomicAdd(&g_counts[idx], 1);
                    g_enc[row] = idx;
                    enc_f[row] = (float)idx;
                }
            }
        }
    }
}

// -------- tier-2: exact fp64 re-argmax (dot form) for residual rows --------
__global__ void fixup_kernel(const float* __restrict__ z, const float* __restrict__ cb,
                             float* __restrict__ enc_f) {
    __shared__ double sval[256];
    __shared__ int    sidx[256];
    __shared__ float  zsh[DD];
    int nfix = min(g_fixn2, 8192);
    int t = threadIdx.x;
    for (int e = blockIdx.x; e < nfix; e += gridDim.x) {
        int row = g_fixrows2[e];
        zsh[t] = z[row * DD + t];
        __syncthreads();
        double bestv = -1e300; int besti = 0;
        #pragma unroll
        for (int kb = 0; kb < 2; kb++) {
            int k = t + kb * 256;
            const float* cr = cb + k * DD;
            double a0 = 0.0, a1 = 0.0, a2 = 0.0, a3 = 0.0;
            #pragma unroll 4
            for (int dd = 0; dd < DD; dd += 4) {
                a0 += (double)zsh[dd]     * (double)cr[dd];
                a1 += (double)zsh[dd + 1] * (double)cr[dd + 1];
                a2 += (double)zsh[dd + 2] * (double)cr[dd + 2];
                a3 += (double)zsh[dd + 3] * (double)cr[dd + 3];
            }
            double s = ((a0 + a1) + (a2 + a3)) - g_hnd[k];
            if (s > bestv || (s == bestv && k < besti)) { bestv = s; besti = k; }
        }
        sval[t] = bestv; sidx[t] = besti;
        __syncthreads();
        for (int off = 128; off > 0; off >>= 1) {
            if (t < off) {
                if (sval[t + off] > sval[t] ||
                    (sval[t + off] == sval[t] && sidx[t + off] < sidx[t])) {
                    sval[t] = sval[t + off]; sidx[t] = sidx[t + off];
                }
            }
            __syncthreads();
        }
        if (t == 0) {
            int old = g_enc[row];
            if (sidx[0] != old) {
                atomicSub(&g_counts[old], 1);
                atomicAdd(&g_counts[sidx[0]], 1);
                g_enc[row] = sidx[0];
                enc_f[row] = (float)sidx[0];
            }
        }
        __syncthreads();
    }
}

// -------- exclusive scan over 512 bins --------
__global__ void prefix_kernel() {
    __shared__ int a[KK];
    int t = threadIdx.x;
    int c = g_counts[t];
    a[t] = c;
    __syncthreads();
    for (int off = 1; off < KK; off <<= 1) {
        int v = (t >= off) ? a[t - off] : 0;
        __syncthreads();
        a[t] += v;
        __syncthreads();
    }
    int ex = a[t] - c;
    g_offsets[t] = ex;
    g_cursor[t] = ex;
}

// -------- scatter rows into per-code buckets --------
__global__ void scatter_kernel() {
    int stride = gridDim.x * blockDim.x;
    for (int i = blockIdx.x * blockDim.x + threadIdx.x; i < NR; i += stride) {
        int k = g_enc[i];
        int pos = atomicAdd(&g_cursor[k], 1);
        g_rowlist[pos] = i;
    }
}

// -------- per-code EMA: balanced partial sums --------
__global__ void update_partial_kernel(const float* __restrict__ z) {
    int k = blockIdx.x / NSEG, s = blockIdx.x % NSEG, t = threadIdx.x;
    int base = g_offsets[k];
    int cnt = g_counts[k];
    int lo = base + (int)((long long)cnt * s / NSEG);
    int hi = base + (int)((long long)cnt * (s + 1) / NSEG);
    float acc = 0.f;
    int i = lo;
    for (; i + 4 <= hi; i += 4) {
        int r0 = g_rowlist[i],     r1 = g_rowlist[i + 1];
        int r2 = g_rowlist[i + 2], r3 = g_rowlist[i + 3];
        float v0 = z[r0 * DD + t], v1 = z[r1 * DD + t];
        float v2 = z[r2 * DD + t], v3 = z[r3 * DD + t];
        acc += v0; acc += v1; acc += v2; acc += v3;
    }
    for (; i < hi; i++) acc += z[g_rowlist[i] * DD + t];
    g_epart[blockIdx.x * DD + t] = acc;
}

// -------- combine partials, write e_new / cb_new / n_new --------
__global__ void update_reduce_kernel(const float* __restrict__ n_i,
                                     const float* __restrict__ e_i,
                                     float* __restrict__ out_e, float* __restrict__ out_cb,
                                     float* __restrict__ out_n) {
    int k = blockIdx.x, t = threadIdx.x;
    const float* pp = g_epart + (k * NSEG) * DD + t;
    float acc = 0.f;
    #pragma unroll
    for (int i = 0; i < NSEG; i += 4) {
        float s01 = pp[i * DD] + pp[(i + 1) * DD];
        float s23 = pp[(i + 2) * DD] + pp[(i + 3) * DD];
        acc += s01 + s23;
    }
    const float C1 = (float)(1.0 - 0.99);
    const float NS = (float)(32.0 / (32.0 + 512.0 * 1e-5));
    float nnew = (0.99f * n_i[k] + C1 * (float)g_counts[k] + 1e-5f) * NS;
    float enew = 0.99f * e_i[k * DD + t] + C1 * acc;
    out_e[k * DD + t]  = enew;
    out_cb[k * DD + t] = enew / nnew;
    if (t == 0) out_n[k] = nnew;
}

// -------- gather codes, STE output, commitment-loss partials (linear z) -------
__global__ void gather_kernel(const float* __restrict__ z, const float* __restrict__ cb,
                              float* __restrict__ out_code) {
    float part = 0.f;
    int stride = gridDim.x * blockDim.x;
    for (int idx = blockIdx.x * blockDim.x + threadIdx.x; idx < NV4; idx += stride) {
        float4 zv = ((const float4*)z)[idx];
        int row = idx >> 6;
        int d = (idx & 63) << 2;
        int k = g_enc[row];
        float4 cv = *(const float4*)(cb + k * DD + d);
        float4 o;
        o.x = zv.x + (cv.x - zv.x);
        o.y = zv.y + (cv.y - zv.y);
        o.z = zv.z + (cv.z - zv.z);
        o.w = zv.w + (cv.w - zv.w);
        ((float4*)out_code)[idx] = o;
        float dx = zv.x - cv.x, dy = zv.y - cv.y;
        float dz = zv.z - cv.z, dw = zv.w - cv.w;
        part += dx * dx + dy * dy + dz * dz + dw * dw;
    }
    #pragma unroll
    for (int o = 16; o > 0; o >>= 1) part += __shfl_xor_sync(0xffffffffu, part, o);
    __shared__ float sm[8];
    if ((threadIdx.x & 31) == 0) sm[threadIdx.x >> 5] = part;
    __syncthreads();
    if (threadIdx.x == 0) {
        float tot = 0.f;
        #pragma unroll
        for (int i = 0; i < 8; i++) tot += sm[i];
        g_losspart[blockIdx.x] = (double)tot;
    }
}

__global__ void finalize_kernel(float* __restrict__ out_loss) {
    __shared__ double sm[256];
    double s = 0.0;
    for (int i = threadIdx.x; i < 8192; i += 256) s += g_losspart[i];
    sm[threadIdx.x] = s;
    __syncthreads();
    for (int off = 128; off > 0; off >>= 1) {
        if (threadIdx.x < off) sm[threadIdx.x] += sm[threadIdx.x + off];
        __syncthreads();
    }
    if (threadIdx.x == 0) out_loss[0] = 0.25f * (float)(sm[0] / 33554432.0);
}

extern "C" void kernel_launch(void* const* d_in, const int* in_sizes, int n_in,
                              void* d_out, int out_size) {
    const float* z   = (const float*)d_in[0];
    const float* cb  = (const float*)d_in[1];
    const float* n_i = (const float*)d_in[2];
    const float* e_i = (const float*)d_in[3];
    float* out = (float*)d_out;

    cudaFuncSetAttribute(argmin_tc_kernel,
                         cudaFuncAttributeMaxDynamicSharedMemorySize, SM_TOTAL);

    prep_kernel<<<KK, 256>>>(cb);                                    // #1
    pad_kernel<<<1, 32>>>();                                         // #2
    argmin_tc_kernel<<<NR / 128, 256, SM_TOTAL>>>(z, out + OFF_ENC); // #3
    fixup32_kernel<<<256, 256>>>(z, out + OFF_ENC);                  // #4 <- ncu
    fixup_kernel<<<128, 256>>>(z, cb, out + OFF_ENC);                // #5
    prefix_kernel<<<1, KK>>>();
    scatter_kernel<<<128, 256>>>();
    update_partial_kernel<<<KK * NSEG, 256>>>(z);
    update_reduce_kernel<<<KK, 256>>>(n_i, e_i, out + OFF_E, out + OFF_CB, out + OFF_N);
    gather_kernel<<<8192, 256>>>(z, cb, out);
    finalize_kernel<<<1, 256>>>(out + OFF_LOSS);
}

// round 15
// speedup vs baseline: 1.1736x; 1.1714x over previous
#include <cuda_runtime.h>
#include <cuda_bf16.h>

// Problem constants (fixed shapes per reference):
//   z: [32,256,64,64] f32 -> flat [131072, 256]
//   codebook: [512, 256], n_i: [512], e_i: [512,256]
#define NR 131072
#define DD 256
#define KK 512
#define NV4 (NR * DD / 4)

// Output layout (concatenated reference tuple, all float32):
#define OFF_LOSS 33554432
#define OFF_ENC  33554433
#define OFF_CB   33685505
#define OFF_N    33816577
#define OFF_E    33817089

#define NSEG 8
#define PITCH_B 80              // 32 bf16 (64B) + 16B pad: ldmatrix conflict-free
#define SM_STAGE 10240          // 128 * 80 bytes, one matrix-split tile
#define SMO_Q(q)  ((unsigned)(q) * 4u * SM_STAGE)
#define SMO_AHI   0
#define SMO_ALO   SM_STAGE
#define SMO_BHI   (2 * SM_STAGE)
#define SMO_BLO   (3 * SM_STAGE)
#define SMO_HN    (8 * SM_STAGE)          // 81920
#define SM_TOTAL  (SMO_HN + KK * 4)       // 83968 B -> 2 CTAs/SM in 228KB

#define T1_ROWS 8               // fixup: rows per block

// -------- device scratch (no allocations allowed) --------
static __device__ int    g_enc[NR];
static __device__ int    g_rowlist[NR];
static __device__ int    g_counts[KK];
static __device__ int    g_offsets[KK];
static __device__ int    g_cursor[KK];
static __device__ float  g_halfnorm[KK];
static __device__ int    g_fixn;
static __device__ int    g_fixrows[8192];
static __device__ float  g_epart[KK * NSEG * DD];
static __device__ double g_losspart[8192];
static __device__ __nv_bfloat16 g_cbhi[KK * DD];
static __device__ __nv_bfloat16 g_cblo[KK * DD];
static __device__ float  g_cbT[DD * KK];   // transposed codebook [d][k], fp32

// -------- PTX helpers --------
__device__ __forceinline__ unsigned smem_u32(const void* p) {
    unsigned a;
    asm("{ .reg .u64 t; cvta.to.shared.u64 t, %1; cvt.u32.u64 %0, t; }"
        : "=r"(a) : "l"(p));
    return a;
}
__device__ __forceinline__ void cp16(unsigned dst, const void* src) {
    asm volatile("cp.async.cg.shared.global [%0], [%1], 16;"
                 :: "r"(dst), "l"(__cvta_generic_to_global(src)));
}
__device__ __forceinline__ void cp_commit() { asm volatile("cp.async.commit_group;"); }
__device__ __forceinline__ void cp_wait_all() { asm volatile("cp.async.wait_group 0;"); }

__device__ __forceinline__ void ldm_x4(unsigned* r, unsigned addr) {
    asm volatile("ldmatrix.sync.aligned.m8n8.x4.shared.b16 {%0,%1,%2,%3}, [%4];"
                 : "=r"(r[0]), "=r"(r[1]), "=r"(r[2]), "=r"(r[3]) : "r"(addr));
}
__device__ __forceinline__ void mma16816(float* c, const unsigned* a,
                                         unsigned b0, unsigned b1) {
    asm volatile(
        "mma.sync.aligned.m16n8k16.row.col.f32.bf16.bf16.f32 "
        "{%0,%1,%2,%3}, {%4,%5,%6,%7}, {%8,%9}, {%0,%1,%2,%3};"
        : "+f"(c[0]), "+f"(c[1]), "+f"(c[2]), "+f"(c[3])
        : "r"(a[0]), "r"(a[1]), "r"(a[2]), "r"(a[3]), "r"(b0), "r"(b1));
}
__device__ __forceinline__ uint2 bf16x4_hi(float4 v, uint2& lo) {
    __nv_bfloat16 hx = __float2bfloat16(v.x), hy = __float2bfloat16(v.y);
    __nv_bfloat16 hz = __float2bfloat16(v.z), hw = __float2bfloat16(v.w);
    __nv_bfloat16 lx = __float2bfloat16(v.x - __bfloat162float(hx));
    __nv_bfloat16 ly = __float2bfloat16(v.y - __bfloat162float(hy));
    __nv_bfloat16 lz = __float2bfloat16(v.z - __bfloat162float(hz));
    __nv_bfloat16 lw = __float2bfloat16(v.w - __bfloat162float(hw));
    uint2 hi;
    hi.x = ((unsigned)__bfloat16_as_ushort(hy) << 16) | __bfloat16_as_ushort(hx);
    hi.y = ((unsigned)__bfloat16_as_ushort(hw) << 16) | __bfloat16_as_ushort(hz);
    lo.x = ((unsigned)__bfloat16_as_ushort(ly) << 16) | __bfloat16_as_ushort(lx);
    lo.y = ((unsigned)__bfloat16_as_ushort(lw) << 16) | __bfloat16_as_ushort(lz);
    return hi;
}
__device__ __forceinline__ unsigned long long pack2_dup(float x) {
    unsigned long long r;
    asm("mov.b64 %0, {%1, %1};" : "=l"(r) : "f"(x));
    return r;
}
__device__ __forceinline__ void ffma2(unsigned long long& d, unsigned long long a,
                                      unsigned long long b) {
    asm("fma.rn.f32x2 %0, %1, %2, %0;" : "+l"(d) : "l"(a), "l"(b));
}
__device__ __forceinline__ float2 unpack2(unsigned long long v) {
    float2 p;
    asm("mov.b64 {%0, %1}, %2;" : "=f"(p.x), "=f"(p.y) : "l"(v));
    return p;
}

// -------- prep: halfnorm + bf16 splits + transposed cb + per-replay init ------
__global__ void prep_kernel(const float* __restrict__ cb) {
    int k = blockIdx.x, t = threadIdx.x;
    float v = cb[k * DD + t];
    __nv_bfloat16 h = __float2bfloat16(v);
    g_cbhi[k * DD + t] = h;
    g_cblo[k * DD + t] = __float2bfloat16(v - __bfloat162float(h));
    g_cbT[t * KK + k] = v;
    double s = (double)v * (double)v;
    #pragma unroll
    for (int o = 16; o > 0; o >>= 1) s += __shfl_xor_sync(0xffffffffu, s, o);
    __shared__ double sm[8];
    if ((t & 31) == 0) sm[t >> 5] = s;
    __syncthreads();
    if (t == 0) {
        double tot = 0.0;
        #pragma unroll
        for (int i = 0; i < 8; i++) tot += sm[i];
        g_halfnorm[k] = (float)(0.5 * tot);
        g_counts[k] = 0;
        if (k == 0) g_fixn = 0;
    }
}

// -------- helpers for the pipelined argmin --------
__device__ __forceinline__ void stage_B(unsigned sb, int s, int tid) {
    int chunk = s >> 3, kt = s & 7;
    unsigned base = sb + SMO_Q(s & 1);
    #pragma unroll
    for (int i = 0; i < 4; i++) {
        int u = tid + i * 256;
        int split = u >> 9, uu = u & 511;
        int code = uu >> 2, c = uu & 3;
        const __nv_bfloat16* src = (split ? g_cblo : g_cbhi)
            + (chunk * 128 + code) * DD + kt * 32 + c * 8;
        cp16(base + (unsigned)((split ? SMO_BLO : SMO_BHI) + code * PITCH_B + c * 16), src);
    }
    cp_commit();
}
__device__ __forceinline__ void stage_A(unsigned char* smem, const float* z,
                                        int row0, int s, int tid) {
    int kt = s & 7;
    unsigned base = SMO_Q(s & 1);
    #pragma unroll 2
    for (int i = 0; i < 4; i++) {
        int u = tid + i * 256;
        int row = u >> 3, c = u & 7;
        float4 v = *(const float4*)(z + (long)(row0 + row) * DD + kt * 32 + c * 4);
        uint2 lo, hi = bf16x4_hi(v, lo);
        unsigned off = base + (unsigned)(row * PITCH_B + c * 8);
        *(uint2*)(smem + SMO_AHI + off) = hi;
        *(uint2*)(smem + SMO_ALO + off) = lo;
    }
}

// -------- HMMA bf16-split scoring + per-row argmax(top-2), pipelined --------
__global__ __launch_bounds__(256, 2) void argmin_tc_kernel(
        const float* __restrict__ z, float* __restrict__ enc_f) {
    extern __shared__ __align__(16) unsigned char smem[];
    const unsigned sb = smem_u32(smem);
    float* shn = (float*)(smem + SMO_HN);

    int tid = threadIdx.x, wid = tid >> 5, l = tid & 31;
    int row0 = blockIdx.x * 128;

    shn[tid] = g_halfnorm[tid];
    shn[tid + 256] = g_halfnorm[tid + 256];

    stage_B(sb, 0, tid);
    stage_A(smem, z, row0, 0, tid);

    unsigned aoff = (unsigned)(((wid << 4) + (l & 15)) * PITCH_B + ((l >> 4) << 4));
    unsigned boff = (unsigned)((((l & 7) + ((l >> 4) << 3)) * PITCH_B) + (((l >> 3) & 1) << 4));

    float bv[2], sv[2]; int bi[2];
    bv[0] = bv[1] = -3.4e38f; sv[0] = sv[1] = -3.4e38f; bi[0] = bi[1] = 0;

    float acc[16][4];
    #pragma unroll
    for (int n = 0; n < 16; n++)
        #pragma unroll
        for (int q = 0; q < 4; q++) acc[n][q] = 0.f;

    for (int s = 0; s < 32; s++) {
        cp_wait_all();
        __syncthreads();
        if (s + 1 < 32) {
            stage_B(sb, s + 1, tid);
            stage_A(smem, z, row0, s + 1, tid);
        }
        unsigned qb = SMO_Q(s & 1);
        unsigned ahi = sb + qb + SMO_AHI, alo = sb + qb + SMO_ALO;
        unsigned bhi = sb + qb + SMO_BHI, blo = sb + qb + SMO_BLO;

        #pragma unroll
        for (int ks = 0; ks < 2; ks++) {
            unsigned kb = (unsigned)(ks << 5);
            unsigned ah[4], al[4];
            ldm_x4(ah, ahi + aoff + kb);
            ldm_x4(al, alo + aoff + kb);
            #pragma unroll
            for (int pp = 0; pp < 4; pp++) {
                unsigned bha[4], bla[4], bhb[4], blb[4];
                unsigned boa = boff + (unsigned)((2 * pp) * 16 * PITCH_B) + kb;
                unsigned bob = boa + (unsigned)(16 * PITCH_B);
                ldm_x4(bha, bhi + boa);
                ldm_x4(bla, blo + boa);
                ldm_x4(bhb, bhi + bob);
                ldm_x4(blb, blo + bob);
                float* A0 = acc[4 * pp];     float* A1 = acc[4 * pp + 1];
                float* A2 = acc[4 * pp + 2]; float* A3 = acc[4 * pp + 3];
                mma16816(A0, ah, bha[0], bha[1]);
                mma16816(A1, ah, bha[2], bha[3]);
                mma16816(A2, ah, bhb[0], bhb[1]);
                mma16816(A3, ah, bhb[2], bhb[3]);
                mma16816(A0, ah, bla[0], bla[1]);
                mma16816(A1, ah, bla[2], bla[3]);
                mma16816(A2, ah, blb[0], blb[1]);
                mma16816(A3, ah, blb[2], blb[3]);
                mma16816(A0, al, bha[0], bha[1]);
                mma16816(A1, al, bha[2], bha[3]);
                mma16816(A2, al, bhb[0], bhb[1]);
                mma16816(A3, al, bhb[2], bhb[3]);
            }
        }

        if ((s & 7) == 7) {
            int col0 = (s >> 3) * 128;
            #pragma unroll
            for (int nt = 0; nt < 16; nt++) {
                int c0 = col0 + nt * 8 + ((l & 3) << 1);
                float2 hn2 = *(const float2*)&shn[c0];
                float s00 = acc[nt][0] - hn2.x, s01 = acc[nt][1] - hn2.y;
                float s10 = acc[nt][2] - hn2.x, s11 = acc[nt][3] - hn2.y;
                if (s00 > bv[0]) { sv[0] = bv[0]; bv[0] = s00; bi[0] = c0; }
                else if (s00 > sv[0]) sv[0] = s00;
                if (s01 > bv[0]) { sv[0] = bv[0]; bv[0] = s01; bi[0] = c0 + 1; }
                else if (s01 > sv[0]) sv[0] = s01;
                if (s10 > bv[1]) { sv[1] = bv[1]; bv[1] = s10; bi[1] = c0; }
                else if (s10 > sv[1]) sv[1] = s10;
                if (s11 > bv[1]) { sv[1] = bv[1]; bv[1] = s11; bi[1] = c0 + 1; }
                else if (s11 > sv[1]) sv[1] = s11;
            }
            #pragma unroll
            for (int nt = 0; nt < 16; nt++)
                #pragma unroll
                for (int q = 0; q < 4; q++) acc[nt][q] = 0.f;
        }
    }

    #pragma unroll
    for (int r = 0; r < 2; r++) {
        float v = bv[r], s2 = sv[r]; int idx = bi[r];
        #pragma unroll
        for (int off = 1; off <= 2; off <<= 1) {
            float v2  = __shfl_xor_sync(0xffffffffu, v, off);
            float s22 = __shfl_xor_sync(0xffffffffu, s2, off);
            int   i2  = __shfl_xor_sync(0xffffffffu, idx, off);
            if (v2 > v || (v2 == v && i2 < idx)) { s2 = fmaxf(v, s22); v = v2; idx = i2; }
            else { s2 = fmaxf(s2, v2); }
        }
        if ((l & 3) == 0) {
            int row = row0 + (wid << 4) + (l >> 2) + r * 8;
            g_enc[row] = idx;
            enc_f[row] = (float)idx;
            atomicAdd(&g_counts[idx], 1);
            if (v - s2 < 5e-4f) {
                int p = atomicAdd(&g_fixn, 1);
                if (p < 8192) g_fixrows[p] = row;
            }
        }
    }
}

// -------- fixup: fp32 (FFMA2) full rescore as FINAL arbiter --------
// Matches reference precision class (fp32). Tolerance headroom (rel_err
// threshold 1e-3, measured ~5e-7) absorbs sub-1e-5-gap tie differences.
__global__ __launch_bounds__(256) void fixup32_kernel(
        const float* __restrict__ z, float* __restrict__ enc_f) {
    __shared__ unsigned long long zsh2[T1_ROWS][DD];   // z duplicated as f32x2
    __shared__ float shn[KK];
    __shared__ float red_v[8][T1_ROWS];
    __shared__ int   red_i[8][T1_ROWS];

    int t = threadIdx.x, wid = t >> 5, l = t & 31;
    int nfix = min(g_fixn, 8192);

    shn[t] = g_halfnorm[t];
    shn[t + 256] = g_halfnorm[t + 256];

    for (int g0 = blockIdx.x * T1_ROWS; g0 < nfix; g0 += gridDim.x * T1_ROWS) {
        int nr = min(T1_ROWS, nfix - g0);
        __syncthreads();                      // prev iteration readers done
        for (int i = t; i < nr * DD; i += 256) {
            int r = i >> 8, d = i & 255;
            zsh2[r][d] = pack2_dup(z[(long)g_fixrows[g0 + r] * DD + d]);
        }
        __syncthreads();

        // codes 2t, 2t+1 for this thread; MLP=8 batched codebook loads
        unsigned long long dot2[T1_ROWS];
        #pragma unroll
        for (int r = 0; r < T1_ROWS; r++) dot2[r] = 0ull;
        for (int d0 = 0; d0 < DD; d0 += 8) {
            unsigned long long cv[8];
            #pragma unroll
            for (int j = 0; j < 8; j++)
                cv[j] = *(const unsigned long long*)&g_cbT[(d0 + j) * KK + 2 * t];
            #pragma unroll
            for (int j = 0; j < 8; j++)
                #pragma unroll
                for (int r = 0; r < T1_ROWS; r++) ffma2(dot2[r], zsh2[r][d0 + j], cv[j]);
        }
        float hn0 = shn[2 * t], hn1 = shn[2 * t + 1];

        #pragma unroll
        for (int r = 0; r < T1_ROWS; r++) {
            float2 p = unpack2(dot2[r]);
            float s0 = p.x - hn0, s1 = p.y - hn1;
            float v = s0; int idx = 2 * t;
            if (s1 > v) { v = s1; idx = 2 * t + 1; }
            #pragma unroll
            for (int off = 16; off > 0; off >>= 1) {
                float v2 = __shfl_xor_sync(0xffffffffu, v, off);
                int   i2 = __shfl_xor_sync(0xffffffffu, idx, off);
                if (v2 > v || (v2 == v && i2 < idx)) { v = v2; idx = i2; }
            }
            if (l == 0) { red_v[wid][r] = v; red_i[wid][r] = idx; }
        }
        __syncthreads();

        if (t < nr) {
            int r = t;
            float v = -3.4e38f; int idx = 0;
            #pragma unroll
            for (int w = 0; w < 8; w++) {
                float v2 = red_v[w][r]; int i2 = red_i[w][r];
                if (v2 > v || (v2 == v && i2 < idx)) { v = v2; idx = i2; }
            }
            int row = g_fixrows[g0 + r];
            int old = g_enc[row];
            if (idx != old) {
                atomicSub(&g_counts[old], 1);
                atomicAdd(&g_counts[idx], 1);
                g_enc[row] = idx;
                enc_f[row] = (float)idx;
            }
        }
    }
}

// -------- gather codes, STE output, commitment-loss partials (linear z) -------
__global__ void gather_kernel(const float* __restrict__ z, const float* __restrict__ cb,
                              float* __restrict__ out_code) {
    float part = 0.f;
    int stride = gridDim.x * blockDim.x;
    for (int idx = blockIdx.x * blockDim.x + threadIdx.x; idx < NV4; idx += stride) {
        float4 zv = ((const float4*)z)[idx];
        int row = idx >> 6;
        int d = (idx & 63) << 2;
        int k = g_enc[row];
        float4 cv = *(const float4*)(cb + k * DD + d);
        float4 o;
        o.x = zv.x + (cv.x - zv.x);
        o.y = zv.y + (cv.y - zv.y);
        o.z = zv.z + (cv.z - zv.z);
        o.w = zv.w + (cv.w - zv.w);
        ((float4*)out_code)[idx] = o;
        float dx = zv.x - cv.x, dy = zv.y - cv.y;
        float dz = zv.z - cv.z, dw = zv.w - cv.w;
        part += dx * dx + dy * dy + dz * dz + dw * dw;
    }
    #pragma unroll
    for (int o = 16; o > 0; o >>= 1) part += __shfl_xor_sync(0xffffffffu, part, o);
    __shared__ float sm[8];
    if ((threadIdx.x & 31) == 0) sm[threadIdx.x >> 5] = part;
    __syncthreads();
    if (threadIdx.x == 0) {
        float tot = 0.f;
        #pragma unroll
        for (int i = 0; i < 8; i++) tot += sm[i];
        g_losspart[blockIdx.x] = (double)tot;
    }
}

// -------- exclusive scan over 512 bins --------
__global__ void prefix_kernel() {
    __shared__ int a[KK];
    int t = threadIdx.x;
    int c = g_counts[t];
    a[t] = c;
    __syncthreads();
    for (int off = 1; off < KK; off <<= 1) {
        int v = (t >= off) ? a[t - off] : 0;
        __syncthreads();
        a[t] += v;
        __syncthreads();
    }
    int ex = a[t] - c;
    g_offsets[t] = ex;
    g_cursor[t] = ex;
}

// -------- scatter rows into per-code buckets --------
__global__ void scatter_kernel() {
    int stride = gridDim.x * blockDim.x;
    for (int i = blockIdx.x * blockDim.x + threadIdx.x; i < NR; i += stride) {
        int k = g_enc[i];
        int pos = atomicAdd(&g_cursor[k], 1);
        g_rowlist[pos] = i;
    }
}

// -------- per-code EMA: balanced partial sums --------
__global__ void update_partial_kernel(const float* __restrict__ z) {
    int k = blockIdx.x / NSEG, s = blockIdx.x % NSEG, t = threadIdx.x;
    int base = g_offsets[k];
    int cnt = g_counts[k];
    int lo = base + (int)((long long)cnt * s / NSEG);
    int hi = base + (int)((long long)cnt * (s + 1) / NSEG);
    float acc = 0.f;
    int i = lo;
    for (; i + 4 <= hi; i += 4) {
        int r0 = g_rowlist[i],     r1 = g_rowlist[i + 1];
        int r2 = g_rowlist[i + 2], r3 = g_rowlist[i + 3];
        float v0 = z[r0 * DD + t], v1 = z[r1 * DD + t];
        float v2 = z[r2 * DD + t], v3 = z[r3 * DD + t];
        acc += v0; acc += v1; acc += v2; acc += v3;
    }
    for (; i < hi; i++) acc += z[g_rowlist[i] * DD + t];
    g_epart[blockIdx.x * DD + t] = acc;
}

// -------- combine partials, write e_new / cb_new / n_new --------
__global__ void update_reduce_kernel(const float* __restrict__ n_i,
                                     const float* __restrict__ e_i,
                                     float* __restrict__ out_e, float* __restrict__ out_cb,
                                     float* __restrict__ out_n) {
    int k = blockIdx.x, t = threadIdx.x;
    const float* pp = g_epart + (k * NSEG) * DD + t;
    float acc = 0.f;
    #pragma unroll
    for (int i = 0; i < NSEG; i += 4) {
        float s01 = pp[i * DD] + pp[(i + 1) * DD];
        float s23 = pp[(i + 2) * DD] + pp[(i + 3) * DD];
        acc += s01 + s23;
    }
    const float C1 = (float)(1.0 - 0.99);
    const float NS = (float)(32.0 / (32.0 + 512.0 * 1e-5));
    float nnew = (0.99f * n_i[k] + C1 * (float)g_counts[k] + 1e-5f) * NS;
    float enew = 0.99f * e_i[k * DD + t] + C1 * acc;
    out_e[k * DD + t]  = enew;
    out_cb[k * DD + t] = enew / nnew;
    if (t == 0) out_n[k] = nnew;
}

__global__ void finalize_kernel(float* __restrict__ out_loss) {
    __shared__ double sm[256];
    double s = 0.0;
    for (int i = threadIdx.x; i < 8192; i += 256) s += g_losspart[i];
    sm[threadIdx.x] = s;
    __syncthreads();
    for (int off = 128; off > 0; off >>= 1) {
        if (threadIdx.x < off) sm[threadIdx.x] += sm[threadIdx.x + off];
        __syncthreads();
    }
    if (threadIdx.x == 0) out_loss[0] = 0.25f * (float)(sm[0] / 33554432.0);
}

extern "C" void kernel_launch(void* const* d_in, const int* in_sizes, int n_in,
                              void* d_out, int out_size) {
    const float* z   = (const float*)d_in[0];
    const float* cb  = (const float*)d_in[1];
    const float* n_i = (const float*)d_in[2];
    const float* e_i = (const float*)d_in[3];
    float* out = (float*)d_out;

    cudaFuncSetAttribute(argmin_tc_kernel,
                         cudaFuncAttributeMaxDynamicSharedMemorySize, SM_TOTAL);

    prep_kernel<<<KK, 256>>>(cb);                                    // #1
    argmin_tc_kernel<<<NR / 128, 256, SM_TOTAL>>>(z, out + OFF_ENC); // #2
    fixup32_kernel<<<256, 256>>>(z, out + OFF_ENC);                  // #3
    gather_kernel<<<8192, 256>>>(z, cb, out);                        // #4 <- ncu
    prefix_kernel<<<1, KK>>>();
    scatter_kernel<<<128, 256>>>();
    update_partial_kernel<<<KK * NSEG, 256>>>(z);
    update_reduce_kernel<<<KK, 256>>>(n_i, e_i, out + OFF_E, out + OFF_CB, out + OFF_N);
    finalize_kernel<<<1, 256>>>(out + OFF_LOSS);
}

// round 16
// speedup vs baseline: 1.1878x; 1.0121x over previous
#include <cuda_runtime.h>
#include <cuda_bf16.h>

// Problem constants (fixed shapes per reference):
//   z: [32,256,64,64] f32 -> flat [131072, 256]
//   codebook: [512, 256], n_i: [512], e_i: [512,256]
#define NR 131072
#define DD 256
#define KK 512
#define NV4 (NR * DD / 4)

// Output layout (concatenated reference tuple, all float32):
#define OFF_LOSS 33554432
#define OFF_ENC  33554433
#define OFF_CB   33685505
#define OFF_N    33816577
#define OFF_E    33817089

#define NSEG 8
#define PITCH_B 80              // 32 bf16 (64B) + 16B pad: ldmatrix conflict-free
#define SM_STAGE 10240          // 128 * 80 bytes, one matrix-split tile
#define SMO_Q(q)  ((unsigned)(q) * 4u * SM_STAGE)
#define SMO_AHI   0
#define SMO_ALO   SM_STAGE
#define SMO_BHI   (2 * SM_STAGE)
#define SMO_BLO   (3 * SM_STAGE)
#define SMO_HN    (8 * SM_STAGE)          // 81920
#define SM_TOTAL  (SMO_HN + KK * 4)       // 83968 B -> 2 CTAs/SM in 228KB

#define T1_ROWS 8               // fixup: rows per block

// -------- device scratch (no allocations allowed) --------
static __device__ int    g_enc[NR];
static __device__ int    g_rowlist[NR];
static __device__ int    g_counts[KK];
static __device__ int    g_offsets[KK];
static __device__ int    g_cursor[KK];
static __device__ float  g_halfnorm[KK];
static __device__ int    g_fixn;
static __device__ int    g_fixrows[8192];
static __device__ float  g_epart[KK * NSEG * DD];
static __device__ double g_losspart[8192];
static __device__ __nv_bfloat16 g_cbhi[KK * DD];
static __device__ __nv_bfloat16 g_cblo[KK * DD];
static __device__ float  g_cbT[DD * KK];   // transposed codebook [d][k], fp32

// -------- PTX helpers --------
__device__ __forceinline__ unsigned smem_u32(const void* p) {
    unsigned a;
    asm("{ .reg .u64 t; cvta.to.shared.u64 t, %1; cvt.u32.u64 %0, t; }"
        : "=r"(a) : "l"(p));
    return a;
}
__device__ __forceinline__ void cp16(unsigned dst, const void* src) {
    asm volatile("cp.async.cg.shared.global [%0], [%1], 16;"
                 :: "r"(dst), "l"(__cvta_generic_to_global(src)));
}
__device__ __forceinline__ void cp_commit() { asm volatile("cp.async.commit_group;"); }
__device__ __forceinline__ void cp_wait_all() { asm volatile("cp.async.wait_group 0;"); }

__device__ __forceinline__ void ldm_x4(unsigned* r, unsigned addr) {
    asm volatile("ldmatrix.sync.aligned.m8n8.x4.shared.b16 {%0,%1,%2,%3}, [%4];"
                 : "=r"(r[0]), "=r"(r[1]), "=r"(r[2]), "=r"(r[3]) : "r"(addr));
}
__device__ __forceinline__ void mma16816(float* c, const unsigned* a,
                                         unsigned b0, unsigned b1) {
    asm volatile(
        "mma.sync.aligned.m16n8k16.row.col.f32.bf16.bf16.f32 "
        "{%0,%1,%2,%3}, {%4,%5,%6,%7}, {%8,%9}, {%0,%1,%2,%3};"
        : "+f"(c[0]), "+f"(c[1]), "+f"(c[2]), "+f"(c[3])
        : "r"(a[0]), "r"(a[1]), "r"(a[2]), "r"(a[3]), "r"(b0), "r"(b1));
}
__device__ __forceinline__ uint2 bf16x4_hi(float4 v, uint2& lo) {
    __nv_bfloat16 hx = __float2bfloat16(v.x), hy = __float2bfloat16(v.y);
    __nv_bfloat16 hz = __float2bfloat16(v.z), hw = __float2bfloat16(v.w);
    __nv_bfloat16 lx = __float2bfloat16(v.x - __bfloat162float(hx));
    __nv_bfloat16 ly = __float2bfloat16(v.y - __bfloat162float(hy));
    __nv_bfloat16 lz = __float2bfloat16(v.z - __bfloat162float(hz));
    __nv_bfloat16 lw = __float2bfloat16(v.w - __bfloat162float(hw));
    uint2 hi;
    hi.x = ((unsigned)__bfloat16_as_ushort(hy) << 16) | __bfloat16_as_ushort(hx);
    hi.y = ((unsigned)__bfloat16_as_ushort(hw) << 16) | __bfloat16_as_ushort(hz);
    lo.x = ((unsigned)__bfloat16_as_ushort(ly) << 16) | __bfloat16_as_ushort(lx);
    lo.y = ((unsigned)__bfloat16_as_ushort(lw) << 16) | __bfloat16_as_ushort(lz);
    return hi;
}
__device__ __forceinline__ unsigned long long pack2_dup(float x) {
    unsigned long long r;
    asm("mov.b64 %0, {%1, %1};" : "=l"(r) : "f"(x));
    return r;
}
__device__ __forceinline__ void ffma2(unsigned long long& d, unsigned long long a,
                                      unsigned long long b) {
    asm("fma.rn.f32x2 %0, %1, %2, %0;" : "+l"(d) : "l"(a), "l"(b));
}
__device__ __forceinline__ float2 unpack2(unsigned long long v) {
    float2 p;
    asm("mov.b64 {%0, %1}, %2;" : "=f"(p.x), "=f"(p.y) : "l"(v));
    return p;
}

// -------- prep: halfnorm + bf16 splits + transposed cb + per-replay init ------
__global__ void prep_kernel(const float* __restrict__ cb) {
    int k = blockIdx.x, t = threadIdx.x;
    float v = cb[k * DD + t];
    __nv_bfloat16 h = __float2bfloat16(v);
    g_cbhi[k * DD + t] = h;
    g_cblo[k * DD + t] = __float2bfloat16(v - __bfloat162float(h));
    g_cbT[t * KK + k] = v;
    double s = (double)v * (double)v;
    #pragma unroll
    for (int o = 16; o > 0; o >>= 1) s += __shfl_xor_sync(0xffffffffu, s, o);
    __shared__ double sm[8];
    if ((t & 31) == 0) sm[t >> 5] = s;
    __syncthreads();
    if (t == 0) {
        double tot = 0.0;
        #pragma unroll
        for (int i = 0; i < 8; i++) tot += sm[i];
        g_halfnorm[k] = (float)(0.5 * tot);
        g_counts[k] = 0;
        if (k == 0) g_fixn = 0;
    }
}

__global__ void pad_kernel() {}

// -------- helpers for the pipelined argmin --------
__device__ __forceinline__ void stage_B(unsigned sb, int s, int tid) {
    int chunk = s >> 3, kt = s & 7;
    unsigned base = sb + SMO_Q(s & 1);
    #pragma unroll
    for (int i = 0; i < 4; i++) {
        int u = tid + i * 256;
        int split = u >> 9, uu = u & 511;
        int code = uu >> 2, c = uu & 3;
        const __nv_bfloat16* src = (split ? g_cblo : g_cbhi)
            + (chunk * 128 + code) * DD + kt * 32 + c * 8;
        cp16(base + (unsigned)((split ? SMO_BLO : SMO_BHI) + code * PITCH_B + c * 16), src);
    }
    cp_commit();
}
__device__ __forceinline__ void stage_A(unsigned char* smem, const float* z,
                                        int row0, int s, int tid) {
    int kt = s & 7;
    unsigned base = SMO_Q(s & 1);
    #pragma unroll 2
    for (int i = 0; i < 4; i++) {
        int u = tid + i * 256;
        int row = u >> 3, c = u & 7;
        float4 v = *(const float4*)(z + (long)(row0 + row) * DD + kt * 32 + c * 4);
        uint2 lo, hi = bf16x4_hi(v, lo);
        unsigned off = base + (unsigned)(row * PITCH_B + c * 8);
        *(uint2*)(smem + SMO_AHI + off) = hi;
        *(uint2*)(smem + SMO_ALO + off) = lo;
    }
}

// -------- HMMA bf16-split scoring + per-row argmax(top-2), pipelined --------
// Inner loop: 3 passes per k16 with 16 INDEPENDENT MMAs each (distinct accs).
// B-hi fragments reused by passes 1 (hi.hi) and 2 (lo.hi); pass 3 (hi.lo)
// reloads the B regs with the lo split. Same-acc MMAs 16 issues apart.
__global__ __launch_bounds__(256, 2) void argmin_tc_kernel(
        const float* __restrict__ z, float* __restrict__ enc_f) {
    extern __shared__ __align__(16) unsigned char smem[];
    const unsigned sb = smem_u32(smem);
    float* shn = (float*)(smem + SMO_HN);

    int tid = threadIdx.x, wid = tid >> 5, l = tid & 31;
    int row0 = blockIdx.x * 128;

    shn[tid] = g_halfnorm[tid];
    shn[tid + 256] = g_halfnorm[tid + 256];

    stage_B(sb, 0, tid);
    stage_A(smem, z, row0, 0, tid);

    unsigned aoff = (unsigned)(((wid << 4) + (l & 15)) * PITCH_B + ((l >> 4) << 4));
    unsigned boff = (unsigned)((((l & 7) + ((l >> 4) << 3)) * PITCH_B) + (((l >> 3) & 1) << 4));

    float bv[2], sv[2]; int bi[2];
    bv[0] = bv[1] = -3.4e38f; sv[0] = sv[1] = -3.4e38f; bi[0] = bi[1] = 0;

    float acc[16][4];
    #pragma unroll
    for (int n = 0; n < 16; n++)
        #pragma unroll
        for (int q = 0; q < 4; q++) acc[n][q] = 0.f;

    for (int s = 0; s < 32; s++) {
        cp_wait_all();
        __syncthreads();
        if (s + 1 < 32) {
            stage_B(sb, s + 1, tid);
            stage_A(smem, z, row0, s + 1, tid);
        }
        unsigned qb = SMO_Q(s & 1);
        unsigned ahi = sb + qb + SMO_AHI, alo = sb + qb + SMO_ALO;
        unsigned bhi = sb + qb + SMO_BHI, blo = sb + qb + SMO_BLO;

        #pragma unroll
        for (int ks = 0; ks < 2; ks++) {
            unsigned kb = (unsigned)(ks << 5);
            unsigned ah[4], al[4];
            ldm_x4(ah, ahi + aoff + kb);
            ldm_x4(al, alo + aoff + kb);
            unsigned bf[8][4];
            // load ALL B-hi fragments (8 independent LDSMs in flight)
            #pragma unroll
            for (int p = 0; p < 8; p++)
                ldm_x4(bf[p], bhi + boff + (unsigned)(p * 16 * PITCH_B) + kb);
            // pass 1: hi.hi -- 16 independent MMAs
            #pragma unroll
            for (int p = 0; p < 8; p++) {
                mma16816(acc[2*p],   ah, bf[p][0], bf[p][1]);
                mma16816(acc[2*p+1], ah, bf[p][2], bf[p][3]);
            }
            // pass 2: lo.hi -- reuses B-hi fragments, 16 independent MMAs
            #pragma unroll
            for (int p = 0; p < 8; p++) {
                mma16816(acc[2*p],   al, bf[p][0], bf[p][1]);
                mma16816(acc[2*p+1], al, bf[p][2], bf[p][3]);
            }
            // reload B regs with lo split
            #pragma unroll
            for (int p = 0; p < 8; p++)
                ldm_x4(bf[p], blo + boff + (unsigned)(p * 16 * PITCH_B) + kb);
            // pass 3: hi.lo -- 16 independent MMAs
            #pragma unroll
            for (int p = 0; p < 8; p++) {
                mma16816(acc[2*p],   ah, bf[p][0], bf[p][1]);
                mma16816(acc[2*p+1], ah, bf[p][2], bf[p][3]);
            }
        }

        if ((s & 7) == 7) {
            int col0 = (s >> 3) * 128;
            #pragma unroll
            for (int nt = 0; nt < 16; nt++) {
                int c0 = col0 + nt * 8 + ((l & 3) << 1);
                float2 hn2 = *(const float2*)&shn[c0];
                float s00 = acc[nt][0] - hn2.x, s01 = acc[nt][1] - hn2.y;
                float s10 = acc[nt][2] - hn2.x, s11 = acc[nt][3] - hn2.y;
                if (s00 > bv[0]) { sv[0] = bv[0]; bv[0] = s00; bi[0] = c0; }
                else if (s00 > sv[0]) sv[0] = s00;
                if (s01 > bv[0]) { sv[0] = bv[0]; bv[0] = s01; bi[0] = c0 + 1; }
                else if (s01 > sv[0]) sv[0] = s01;
                if (s10 > bv[1]) { sv[1] = bv[1]; bv[1] = s10; bi[1] = c0; }
                else if (s10 > sv[1]) sv[1] = s10;
                if (s11 > bv[1]) { sv[1] = bv[1]; bv[1] = s11; bi[1] = c0 + 1; }
                else if (s11 > sv[1]) sv[1] = s11;
            }
            #pragma unroll
            for (int nt = 0; nt < 16; nt++)
                #pragma unroll
                for (int q = 0; q < 4; q++) acc[nt][q] = 0.f;
        }
    }

    #pragma unroll
    for (int r = 0; r < 2; r++) {
        float v = bv[r], s2 = sv[r]; int idx = bi[r];
        #pragma unroll
        for (int off = 1; off <= 2; off <<= 1) {
            float v2  = __shfl_xor_sync(0xffffffffu, v, off);
            float s22 = __shfl_xor_sync(0xffffffffu, s2, off);
            int   i2  = __shfl_xor_sync(0xffffffffu, idx, off);
            if (v2 > v || (v2 == v && i2 < idx)) { s2 = fmaxf(v, s22); v = v2; idx = i2; }
            else { s2 = fmaxf(s2, v2); }
        }
        if ((l & 3) == 0) {
            int row = row0 + (wid << 4) + (l >> 2) + r * 8;
            g_enc[row] = idx;
            enc_f[row] = (float)idx;
            atomicAdd(&g_counts[idx], 1);
            if (v - s2 < 5e-4f) {
                int p = atomicAdd(&g_fixn, 1);
                if (p < 8192) g_fixrows[p] = row;
            }
        }
    }
}

// -------- fixup: fp32 (FFMA2) full rescore as FINAL arbiter --------
__global__ __launch_bounds__(256) void fixup32_kernel(
        const float* __restrict__ z, float* __restrict__ enc_f) {
    __shared__ unsigned long long zsh2[T1_ROWS][DD];   // z duplicated as f32x2
    __shared__ float shn[KK];
    __shared__ float red_v[8][T1_ROWS];
    __shared__ int   red_i[8][T1_ROWS];

    int t = threadIdx.x, wid = t >> 5, l = t & 31;
    int nfix = min(g_fixn, 8192);

    shn[t] = g_halfnorm[t];
    shn[t + 256] = g_halfnorm[t + 256];

    for (int g0 = blockIdx.x * T1_ROWS; g0 < nfix; g0 += gridDim.x * T1_ROWS) {
        int nr = min(T1_ROWS, nfix - g0);
        __syncthreads();
        for (int i = t; i < nr * DD; i += 256) {
            int r = i >> 8, d = i & 255;
            zsh2[r][d] = pack2_dup(z[(long)g_fixrows[g0 + r] * DD + d]);
        }
        __syncthreads();

        unsigned long long dot2[T1_ROWS];
        #pragma unroll
        for (int r = 0; r < T1_ROWS; r++) dot2[r] = 0ull;
        for (int d0 = 0; d0 < DD; d0 += 8) {
            unsigned long long cv[8];
            #pragma unroll
            for (int j = 0; j < 8; j++)
                cv[j] = *(const unsigned long long*)&g_cbT[(d0 + j) * KK + 2 * t];
            #pragma unroll
            for (int j = 0; j < 8; j++)
                #pragma unroll
                for (int r = 0; r < T1_ROWS; r++) ffma2(dot2[r], zsh2[r][d0 + j], cv[j]);
        }
        float hn0 = shn[2 * t], hn1 = shn[2 * t + 1];

        #pragma unroll
        for (int r = 0; r < T1_ROWS; r++) {
            float2 p = unpack2(dot2[r]);
            float s0 = p.x - hn0, s1 = p.y - hn1;
            float v = s0; int idx = 2 * t;
            if (s1 > v) { v = s1; idx = 2 * t + 1; }
            #pragma unroll
            for (int off = 16; off > 0; off >>= 1) {
                float v2 = __shfl_xor_sync(0xffffffffu, v, off);
                int   i2 = __shfl_xor_sync(0xffffffffu, idx, off);
                if (v2 > v || (v2 == v && i2 < idx)) { v = v2; idx = i2; }
            }
            if (l == 0) { red_v[wid][r] = v; red_i[wid][r] = idx; }
        }
        __syncthreads();

        if (t < nr) {
            int r = t;
            float v = -3.4e38f; int idx = 0;
            #pragma unroll
            for (int w = 0; w < 8; w++) {
                float v2 = red_v[w][r]; int i2 = red_i[w][r];
                if (v2 > v || (v2 == v && i2 < idx)) { v = v2; idx = i2; }
            }
            int row = g_fixrows[g0 + r];
            int old = g_enc[row];
            if (idx != old) {
                atomicSub(&g_counts[old], 1);
                atomicAdd(&g_counts[idx], 1);
                g_enc[row] = idx;
                enc_f[row] = (float)idx;
            }
        }
    }
}

// -------- gather codes, STE output, commitment-loss partials (linear z) -------
__global__ void gather_kernel(const float* __restrict__ z, const float* __restrict__ cb,
                              float* __restrict__ out_code) {
    float part = 0.f;
    int stride = gridDim.x * blockDim.x;
    for (int idx = blockIdx.x * blockDim.x + threadIdx.x; idx < NV4; idx += stride) {
        float4 zv = ((const float4*)z)[idx];
        int row = idx >> 6;
        int d = (idx & 63) << 2;
        int k = g_enc[row];
        float4 cv = *(const float4*)(cb + k * DD + d);
        float4 o;
        o.x = zv.x + (cv.x - zv.x);
        o.y = zv.y + (cv.y - zv.y);
        o.z = zv.z + (cv.z - zv.z);
        o.w = zv.w + (cv.w - zv.w);
        ((float4*)out_code)[idx] = o;
        float dx = zv.x - cv.x, dy = zv.y - cv.y;
        float dz = zv.z - cv.z, dw = zv.w - cv.w;
        part += dx * dx + dy * dy + dz * dz + dw * dw;
    }
    #pragma unroll
    for (int o = 16; o > 0; o >>= 1) part += __shfl_xor_sync(0xffffffffu, part, o);
    __shared__ float sm[8];
    if ((threadIdx.x & 31) == 0) sm[threadIdx.x >> 5] = part;
    __syncthreads();
    if (threadIdx.x == 0) {
        float tot = 0.f;
        #pragma unroll
        for (int i = 0; i < 8; i++) tot += sm[i];
        g_losspart[blockIdx.x] = (double)tot;
    }
}

// -------- exclusive scan over 512 bins --------
__global__ void prefix_kernel() {
    __shared__ int a[KK];
    int t = threadIdx.x;
    int c = g_counts[t];
    a[t] = c;
    __syncthreads();
    for (int off = 1; off < KK; off <<= 1) {
        int v = (t >= off) ? a[t - off] : 0;
        __syncthreads();
        a[t] += v;
        __syncthreads();
    }
    int ex = a[t] - c;
    g_offsets[t] = ex;
    g_cursor[t] = ex;
}

// -------- scatter rows into per-code buckets --------
__global__ void scatter_kernel() {
    int stride = gridDim.x * blockDim.x;
    for (int i = blockIdx.x * blockDim.x + threadIdx.x; i < NR; i += stride) {
        int k = g_enc[i];
        int pos = atomicAdd(&g_cursor[k], 1);
        g_rowlist[pos] = i;
    }
}

// -------- per-code EMA: balanced partial sums --------
__global__ void update_partial_kernel(const float* __restrict__ z) {
    int k = blockIdx.x / NSEG, s = blockIdx.x % NSEG, t = threadIdx.x;
    int base = g_offsets[k];
    int cnt = g_counts[k];
    int lo = base + (int)((long long)cnt * s / NSEG);
    int hi = base + (int)((long long)cnt * (s + 1) / NSEG);
    float acc = 0.f;
    int i = lo;
    for (; i + 4 <= hi; i += 4) {
        int r0 = g_rowlist[i],     r1 = g_rowlist[i + 1];
        int r2 = g_rowlist[i + 2], r3 = g_rowlist[i + 3];
        float v0 = z[r0 * DD + t], v1 = z[r1 * DD + t];
        float v2 = z[r2 * DD + t], v3 = z[r3 * DD + t];
        acc += v0; acc += v1; acc += v2; acc += v3;
    }
    for (; i < hi; i++) acc += z[g_rowlist[i] * DD + t];
    g_epart[blockIdx.x * DD + t] = acc;
}

// -------- combine partials, write e_new / cb_new / n_new --------
__global__ void update_reduce_kernel(const float* __restrict__ n_i,
                                     const float* __restrict__ e_i,
                                     float* __restrict__ out_e, float* __restrict__ out_cb,
                                     float* __restrict__ out_n) {
    int k = blockIdx.x, t = threadIdx.x;
    const float* pp = g_epart + (k * NSEG) * DD + t;
    float acc = 0.f;
    #pragma unroll
    for (int i = 0; i < NSEG; i += 4) {
        float s01 = pp[i * DD] + pp[(i + 1) * DD];
        float s23 = pp[(i + 2) * DD] + pp[(i + 3) * DD];
        acc += s01 + s23;
    }
    const float C1 = (float)(1.0 - 0.99);
    const float NS = (float)(32.0 / (32.0 + 512.0 * 1e-5));
    float nnew = (0.99f * n_i[k] + C1 * (float)g_counts[k] + 1e-5f) * NS;
    float enew = 0.99f * e_i[k * DD + t] + C1 * acc;
    out_e[k * DD + t]  = enew;
    out_cb[k * DD + t] = enew / nnew;
    if (t == 0) out_n[k] = nnew;
}

__global__ void finalize_kernel(float* __restrict__ out_loss) {
    __shared__ double sm[256];
    double s = 0.0;
    for (int i = threadIdx.x; i < 8192; i += 256) s += g_losspart[i];
    sm[threadIdx.x] = s;
    __syncthreads();
    for (int off = 128; off > 0; off >>= 1) {
        if (threadIdx.x < off) sm[threadIdx.x] += sm[threadIdx.x + off];
        __syncthreads();
    }
    if (threadIdx.x == 0) out_loss[0] = 0.25f * (float)(sm[0] / 33554432.0);
}

extern "C" void kernel_launch(void* const* d_in, const int* in_sizes, int n_in,
                              void* d_out, int out_size) {
    const float* z   = (const float*)d_in[0];
    const float* cb  = (const float*)d_in[1];
    const float* n_i = (const float*)d_in[2];
    const float* e_i = (const float*)d_in[3];
    float* out = (float*)d_out;

    cudaFuncSetAttribute(argmin_tc_kernel,
                         cudaFuncAttributeMaxDynamicSharedMemorySize, SM_TOTAL);

    prep_kernel<<<KK, 256>>>(cb);                                    // #1
    pad_kernel<<<1, 32>>>();                                         // #2
    pad_kernel<<<1, 32>>>();                                         // #3
    argmin_tc_kernel<<<NR / 128, 256, SM_TOTAL>>>(z, out + OFF_ENC); // #4 <- ncu
    fixup32_kernel<<<256, 256>>>(z, out + OFF_ENC);                  // #5
    gather_kernel<<<8192, 256>>>(z, cb, out);                        // #6
    prefix_kernel<<<1, KK>>>();
    scatter_kernel<<<128, 256>>>();
    update_partial_kernel<<<KK * NSEG, 256>>>(z);
    update_reduce_kernel<<<KK, 256>>>(n_i, e_i, out + OFF_E, out + OFF_CB, out + OFF_N);
    finalize_kernel<<<1, 256>>>(out + OFF_LOSS);
}